// round 8
// baseline (speedup 1.0000x reference)
#include <cuda_runtime.h>
#include <cuda_bf16.h>
#include <cstdint>

#define Bb 32
#define Ll 512
#define Dd 512
#define Ss 8

// ---------------------------------------------------------------------------
// Device-global scratch
// ---------------------------------------------------------------------------
__device__ __nv_bfloat16 g_A2hi[(size_t)Bb * Ss * Ll * Dd];
__device__ __nv_bfloat16 g_A2lo[(size_t)Bb * Ss * Ll * Dd];
__device__ __nv_bfloat16 g_A1hi[(size_t)Bb * Ll * Dd];
__device__ __nv_bfloat16 g_A1lo[(size_t)Bb * Ll * Dd];
__device__ __nv_bfloat16 g_B2hi[(size_t)Bb * Ll * Dd];
__device__ __nv_bfloat16 g_B2lo[(size_t)Bb * Ll * Dd];
__device__ __nv_bfloat16 g_Mrhi[(size_t)Ss * Dd * Dd];
__device__ __nv_bfloat16 g_Mrlo[(size_t)Ss * Dd * Dd];
__device__ float g_P1[Bb * Ll * Ss];
__device__ float g_Q1[Bb * Ll * Ss];
__device__ float g_P2t[Bb * Ss * Ll];
__device__ float g_Q2t[Bb * Ss * Ll];

// ---------------------------------------------------------------------------
// Helpers
// ---------------------------------------------------------------------------
__device__ __forceinline__ uint32_t smem_u32(const void* p) {
    uint32_t a;
    asm("{ .reg .u64 t; cvta.to.shared.u64 t, %1; cvt.u32.u64 %0, t; }"
        : "=r"(a) : "l"(p));
    return a;
}
__device__ __forceinline__ void ldsm4(uint32_t* r, uint32_t a) {
    asm volatile("ldmatrix.sync.aligned.m8n8.x4.shared.b16 {%0,%1,%2,%3}, [%4];"
                 : "=r"(r[0]), "=r"(r[1]), "=r"(r[2]), "=r"(r[3]) : "r"(a) : "memory");
}
__device__ __forceinline__ void mma_bf16(float* c, const uint32_t* a, const uint32_t* b) {
    asm volatile("mma.sync.aligned.m16n8k16.row.col.f32.bf16.bf16.f32 "
                 "{%0,%1,%2,%3}, {%4,%5,%6,%7}, {%8,%9}, {%0,%1,%2,%3};"
                 : "+f"(c[0]), "+f"(c[1]), "+f"(c[2]), "+f"(c[3])
                 : "r"(a[0]), "r"(a[1]), "r"(a[2]), "r"(a[3]), "r"(b[0]), "r"(b[1]));
}
#define CP16(dst, src) \
    asm volatile("cp.async.cg.shared.global [%0], [%1], 16;" :: "r"(dst), "l"(src) : "memory")
#define CPCOMMIT() asm volatile("cp.async.commit_group;" ::: "memory")
#define CPWAIT1() asm volatile("cp.async.wait_group 1;" ::: "memory")
#define CPWAIT2() asm volatile("cp.async.wait_group 2;" ::: "memory")

__device__ __forceinline__ uint32_t pack_bf16x2(float a, float b) {
    uint32_t h;
    asm("cvt.rn.bf16x2.f32 %0, %1, %2;" : "=r"(h) : "f"(b), "f"(a));
    return h;
}
__device__ __forceinline__ void split2(float a, float b, uint32_t& h, uint32_t& l) {
    h = pack_bf16x2(a, b);
    float ha = __uint_as_float(h << 16), hb = __uint_as_float(h & 0xFFFF0000u);
    l = pack_bf16x2(a - ha, b - hb);
}

// FMA-pipe-only sigmoid, abs err ~1.5e-5
__device__ __forceinline__ float sig_fma(float x) {
    float ax = fminf(fabsf(x), 20.0f);
    float y = -1.44269504f * ax;
    float t = y + 12582912.0f;
    int n = __float_as_int(t) - 0x4B400000;
    float f = y - (t - 12582912.0f);
    float p = 1.33335581e-3f;
    p = fmaf(p, f, 9.61812910e-3f);
    p = fmaf(p, f, 5.55041086e-2f);
    p = fmaf(p, f, 2.40226507e-1f);
    p = fmaf(p, f, 6.93147181e-1f);
    p = fmaf(p, f, 1.0f);
    float E = __int_as_float(__float_as_int(p) + (n << 23));
    float w = 1.0f + E;
    float r = __int_as_float(0x7EF127EAu - __float_as_int(w));
    r = r * (2.0f - w * r);
    r = r * (2.0f - w * r);
    return x >= 0.0f ? r : 1.0f - r;
}

// ---------------------------------------------------------------------------
// K0: split Mr into bf16 hi/lo
// ---------------------------------------------------------------------------
__global__ void mrsplit_kernel(const float* __restrict__ Mr) {
    size_t i = ((size_t)blockIdx.x * 256 + threadIdx.x) * 4;
    float4 v = *reinterpret_cast<const float4*>(Mr + i);
    uint32_t h0, l0, h1, l1;
    split2(v.x, v.y, h0, l0);
    split2(v.z, v.w, h1, l1);
    *reinterpret_cast<uint2*>(&g_Mrhi[i]) = make_uint2(h0, h1);
    *reinterpret_cast<uint2*>(&g_Mrlo[i]) = make_uint2(l0, l1);
}

// ---------------------------------------------------------------------------
// K1: fused projections + input split. One warp per row.
// ---------------------------------------------------------------------------
__global__ void conv_proj_kernel(const float* __restrict__ arg1,
                                 const float* __restrict__ arg2,
                                 const float* __restrict__ Wg,
                                 const float* __restrict__ V) {
    int w = (blockIdx.x * blockDim.x + threadIdx.x) >> 5;
    int lane = threadIdx.x & 31;
    bool first = (w < Bb * Ll);
    const float* src = first ? arg1 : arg2;
    int row = first ? w : w - Bb * Ll;
    int woff = first ? 0 : Dd;
    __nv_bfloat16* dh = first ? g_A1hi : g_B2hi;
    __nv_bfloat16* dl = first ? g_A1lo : g_B2lo;

    float aw[8] = {0,0,0,0,0,0,0,0}, av[8] = {0,0,0,0,0,0,0,0};
    const float* srow = src + (size_t)row * Dd;
#pragma unroll
    for (int q = 0; q < 4; q++) {
        int d0 = (q * 32 + lane) * 4;
        float4 x = *reinterpret_cast<const float4*>(srow + d0);
        uint32_t h0, l0, h1, l1;
        split2(x.x, x.y, h0, l0);
        split2(x.z, x.w, h1, l1);
        *reinterpret_cast<uint2*>(&dh[(size_t)row * Dd + d0]) = make_uint2(h0, h1);
        *reinterpret_cast<uint2*>(&dl[(size_t)row * Dd + d0]) = make_uint2(l0, l1);
        float xs[4] = {x.x, x.y, x.z, x.w};
#pragma unroll
        for (int e = 0; e < 4; e++) {
            int d = d0 + e;
            const float4* wp = reinterpret_cast<const float4*>(Wg + (size_t)(woff + d) * Ss);
            const float4* vp = reinterpret_cast<const float4*>(V  + (size_t)(woff + d) * Ss);
            float4 w0 = wp[0], w1 = wp[1], v0 = vp[0], v1 = vp[1];
            float xv = xs[e];
            aw[0] += xv*w0.x; aw[1] += xv*w0.y; aw[2] += xv*w0.z; aw[3] += xv*w0.w;
            aw[4] += xv*w1.x; aw[5] += xv*w1.y; aw[6] += xv*w1.z; aw[7] += xv*w1.w;
            av[0] += xv*v0.x; av[1] += xv*v0.y; av[2] += xv*v0.z; av[3] += xv*v0.w;
            av[4] += xv*v1.x; av[5] += xv*v1.y; av[6] += xv*v1.z; av[7] += xv*v1.w;
        }
    }
#pragma unroll
    for (int s = 0; s < 8; s++)
#pragma unroll
        for (int o = 16; o > 0; o >>= 1) {
            aw[s] += __shfl_xor_sync(0xffffffffu, aw[s], o);
            av[s] += __shfl_xor_sync(0xffffffffu, av[s], o);
        }
    if (lane == 0) {
        if (first) {
#pragma unroll
            for (int s = 0; s < 8; s++) {
                g_P1[(size_t)row * Ss + s] = aw[s];
                g_Q1[(size_t)row * Ss + s] = av[s];
            }
        } else {
            int bbv = row >> 9, j = row & 511;
#pragma unroll
            for (int s = 0; s < 8; s++) {
                g_P2t[((size_t)bbv * Ss + s) * Ll + j] = aw[s];
                g_Q2t[((size_t)bbv * Ss + s) * Ll + j] = av[s];
            }
        }
    }
}

// ---------------------------------------------------------------------------
// K2: A2 = arg2 @ Mr^T, 3-pass. CTA 128x128, 512 thr (16 warps, 32m x 32n),
// K-chunk 64, 3-stage cp.async, ONE barrier per chunk, pass-major MMA order.
// ---------------------------------------------------------------------------
#define S1_OP   18432
#define S1_BUF  (4 * S1_OP)
#define S1_SMEM (3 * S1_BUF)

__global__ __launch_bounds__(512, 1) void gemm1_kernel() {
    extern __shared__ char smem[];
    uint32_t sb = smem_u32(smem);
    int t = threadIdx.x, lane = t & 31, wid = t >> 5;
    int bz = blockIdx.z, bbv = bz >> 3, kk = bz & 7;
    int j0 = blockIdx.y * 128, d0 = blockIdx.x * 128;
    int wm = wid & 3, wn = wid >> 2;

    const __nv_bfloat16* srcOp[4] = {
        g_B2hi + ((size_t)bbv * Ll + j0) * Dd,
        g_B2lo + ((size_t)bbv * Ll + j0) * Dd,
        g_Mrhi + ((size_t)kk * Dd + d0) * Dd,
        g_Mrlo + ((size_t)kk * Dd + d0) * Dd};

    int r0 = t >> 3, s0 = t & 7;
    int r1 = (512 + t) >> 3;
    size_t gOff0 = (size_t)r0 * Dd + s0 * 8;
    size_t gOff1 = (size_t)r1 * Dd + s0 * 8;
    uint32_t sOff0 = (uint32_t)(r0 * 144 + s0 * 16);
    uint32_t sOff1 = (uint32_t)(r1 * 144 + s0 * 16);

    auto issue = [&](int c) {
        uint32_t dstb = sb + (c % 3) * S1_BUF;
        int e0 = c * 64;
#pragma unroll
        for (int op = 0; op < 4; op++) {
            CP16(dstb + op * S1_OP + sOff0, srcOp[op] + gOff0 + e0);
            CP16(dstb + op * S1_OP + sOff1, srcOp[op] + gOff1 + e0);
        }
        CPCOMMIT();
    };

    uint32_t aBase[2], bBase[2];
#pragma unroll
    for (int mt = 0; mt < 2; mt++)
        aBase[mt] = (uint32_t)((wm * 32 + mt * 16 + (lane & 15)) * 144 + (lane >> 4) * 16);
#pragma unroll
    for (int nt = 0; nt < 2; nt++)
        bBase[nt] = (uint32_t)((wn * 32 + nt * 16 + (lane & 15)) * 144 + (lane >> 4) * 16);

    float acc[2][4][4];
#pragma unroll
    for (int mt = 0; mt < 2; mt++)
#pragma unroll
        for (int n8 = 0; n8 < 4; n8++)
#pragma unroll
            for (int q = 0; q < 4; q++) acc[mt][n8][q] = 0.f;

    issue(0); issue(1);
#pragma unroll 1
    for (int c = 0; c < 8; c++) {
        CPWAIT1();
        __syncthreads();
        if (c < 6) issue(c + 2); else CPCOMMIT();
        uint32_t bufb = sb + (c % 3) * S1_BUF;
#pragma unroll
        for (int k16 = 0; k16 < 4; k16++) {
            uint32_t kadd = (uint32_t)(k16 * 32);
            uint32_t ahi[2][4], alo[2][4], bhi[2][4], blo[2][4];
#pragma unroll
            for (int mt = 0; mt < 2; mt++) {
                ldsm4(ahi[mt], bufb + aBase[mt] + kadd);
                ldsm4(alo[mt], bufb + S1_OP + aBase[mt] + kadd);
            }
#pragma unroll
            for (int nt = 0; nt < 2; nt++) {
                ldsm4(bhi[nt], bufb + 2 * S1_OP + bBase[nt] + kadd);
                ldsm4(blo[nt], bufb + 3 * S1_OP + bBase[nt] + kadd);
            }
            // pass-major: dependent MMAs on one acc are 8 issues apart
#pragma unroll
            for (int mt = 0; mt < 2; mt++)
#pragma unroll
                for (int n8 = 0; n8 < 4; n8++) {
                    uint32_t bh[2] = {bhi[n8 >> 1][n8 & 1], bhi[n8 >> 1][(n8 & 1) + 2]};
                    mma_bf16(acc[mt][n8], ahi[mt], bh);
                }
#pragma unroll
            for (int mt = 0; mt < 2; mt++)
#pragma unroll
                for (int n8 = 0; n8 < 4; n8++) {
                    uint32_t bl[2] = {blo[n8 >> 1][n8 & 1], blo[n8 >> 1][(n8 & 1) + 2]};
                    mma_bf16(acc[mt][n8], ahi[mt], bl);
                }
#pragma unroll
            for (int mt = 0; mt < 2; mt++)
#pragma unroll
                for (int n8 = 0; n8 < 4; n8++) {
                    uint32_t bh[2] = {bhi[n8 >> 1][n8 & 1], bhi[n8 >> 1][(n8 & 1) + 2]};
                    mma_bf16(acc[mt][n8], alo[mt], bh);
                }
        }
    }

    size_t plane = (size_t)bz * Ll * Dd;
#pragma unroll
    for (int mt = 0; mt < 2; mt++) {
        int jr = j0 + wm * 32 + mt * 16 + (lane >> 2);
#pragma unroll
        for (int n8 = 0; n8 < 4; n8++) {
            int dc = d0 + wn * 32 + n8 * 8 + (lane & 3) * 2;
            size_t x0 = plane + (size_t)jr * Dd + dc;
            size_t x1 = x0 + (size_t)8 * Dd;
            uint32_t h, l;
            split2(acc[mt][n8][0], acc[mt][n8][1], h, l);
            *reinterpret_cast<uint32_t*>(&g_A2hi[x0]) = h;
            *reinterpret_cast<uint32_t*>(&g_A2lo[x0]) = l;
            split2(acc[mt][n8][2], acc[mt][n8][3], h, l);
            *reinterpret_cast<uint32_t*>(&g_A2hi[x1]) = h;
            *reinterpret_cast<uint32_t*>(&g_A2lo[x1]) = l;
        }
    }
}

// ---------------------------------------------------------------------------
// K3: bi = arg1 @ A2^T (8 planes) + fused epilogue.
// CTA 64i x 128j, 512 thr (16 warps 4x4, warp tile 16i x 32j).
// A resident (133KB); B K-chunk 32, 4-stage cp.async (3-chunk prefetch),
// one barrier per chunk. accH/accL split + pass-major MMA order.
// ---------------------------------------------------------------------------
#define S2_AOP   66560                    // 64 * 1040
#define S2_BOP   10240                    // 128 * 80
#define S2_BBUF  (2 * S2_BOP)             // 20480
#define S2_BOFF  (2 * S2_AOP)             // 133120
#define S2_SMEM  (S2_BOFF + 4 * S2_BBUF)  // 215040

__global__ __launch_bounds__(512, 1) void gemm2_kernel(const float* __restrict__ Bg,
                                                       const float* __restrict__ bvec,
                                                       const float* __restrict__ U,
                                                       float* __restrict__ out) {
    extern __shared__ char smem[];
    uint32_t sb = smem_u32(smem);
    int t = threadIdx.x, lane = t & 31, wid = t >> 5;
    int bbv = blockIdx.z, i0 = blockIdx.y * 64, j0 = blockIdx.x * 128;
    int wi = wid & 3, wj = wid >> 2;

    // Resident A (arg1 split): one cp.async group
    {
        const __nv_bfloat16* sA[2] = {g_A1hi + ((size_t)bbv * Ll + i0) * Dd,
                                      g_A1lo + ((size_t)bbv * Ll + i0) * Dd};
#pragma unroll
        for (int i = 0; i < 16; i++) {
            int var = i >> 3;
            int rem = (i & 7) * 512 + t;
            int r = rem >> 6, seg = rem & 63;
            CP16(sb + var * S2_AOP + r * 1040 + seg * 16,
                 sA[var] + (size_t)r * Dd + seg * 8);
        }
        CPCOMMIT();
    }

    // B chunk-32 load offsets: 128 rows x 64B per variant, 1 CP16/thr/variant
    int rB = t >> 2, sB = t & 3;
    size_t gB = (size_t)rB * Dd + sB * 8;
    uint32_t sBo = (uint32_t)(rB * 80 + sB * 16);
    const __nv_bfloat16* bHi = g_A2hi + ((size_t)bbv * 8 * Ll + j0) * Dd;
    const __nv_bfloat16* bLo = g_A2lo + ((size_t)bbv * 8 * Ll + j0) * Dd;

    auto issueB = [&](int m) {
        int k = m >> 4, c = m & 15;
        uint32_t dstb = sb + S2_BOFF + (m & 3) * S2_BBUF;
        size_t base = (size_t)k * Ll * Dd + c * 32;
        CP16(dstb + sBo, bHi + base + gB);
        CP16(dstb + S2_BOP + sBo, bLo + base + gB);
        CPCOMMIT();
    };
    issueB(0); issueB(1); issueB(2);

    uint32_t aBase = (uint32_t)((wi * 16 + (lane & 15)) * 1040 + (lane >> 4) * 16);
    uint32_t bBase[2];
#pragma unroll
    for (int nt = 0; nt < 2; nt++)
        bBase[nt] = (uint32_t)((wj * 32 + nt * 16 + (lane & 15)) * 80 + (lane >> 4) * 16);

    float bU = 0.f;
#pragma unroll
    for (int s = 0; s < 8; s++) bU += bvec[s] * U[s];
    float sc[4][2][2];
#pragma unroll
    for (int nt = 0; nt < 4; nt++)
#pragma unroll
        for (int p = 0; p < 2; p++) { sc[nt][p][0] = bU; sc[nt][p][1] = bU; }

    int iL = i0 + wi * 16 + (lane >> 2);
    int iH = iL + 8;

#pragma unroll 1
    for (int k = 0; k < 8; k++) {
        float accH[4][4], accL[4][4];
#pragma unroll
        for (int n8 = 0; n8 < 4; n8++)
#pragma unroll
            for (int q = 0; q < 4; q++) { accH[n8][q] = 0.f; accL[n8][q] = 0.f; }

#pragma unroll 1
        for (int c = 0; c < 16; c++) {
            int m = k * 16 + c;
            CPWAIT2();
            __syncthreads();
            if (m < 125) issueB(m + 3); else CPCOMMIT();
            uint32_t bufb = sb + S2_BOFF + (m & 3) * S2_BBUF;
#pragma unroll
            for (int k16 = 0; k16 < 2; k16++) {
                uint32_t ahi[4], alo[4], bhi[2][4], blo[2][4];
                uint32_t aoff = aBase + (uint32_t)(c * 64 + k16 * 32);
                ldsm4(ahi, sb + aoff);
                ldsm4(alo, sb + S2_AOP + aoff);
                uint32_t kadd = (uint32_t)(k16 * 32);
#pragma unroll
                for (int nt = 0; nt < 2; nt++) {
                    ldsm4(bhi[nt], bufb + bBase[nt] + kadd);
                    ldsm4(blo[nt], bufb + S2_BOP + bBase[nt] + kadd);
                }
                // pass-major + split accumulators
#pragma unroll
                for (int n8 = 0; n8 < 4; n8++) {
                    uint32_t bh[2] = {bhi[n8 >> 1][n8 & 1], bhi[n8 >> 1][(n8 & 1) + 2]};
                    mma_bf16(accH[n8], ahi, bh);
                }
#pragma unroll
                for (int n8 = 0; n8 < 4; n8++) {
                    uint32_t bl[2] = {blo[n8 >> 1][n8 & 1], blo[n8 >> 1][(n8 & 1) + 2]};
                    mma_bf16(accL[n8], ahi, bl);
                }
#pragma unroll
                for (int n8 = 0; n8 < 4; n8++) {
                    uint32_t bh[2] = {bhi[n8 >> 1][n8 & 1], bhi[n8 >> 1][(n8 & 1) + 2]};
                    mma_bf16(accL[n8], alo, bh);
                }
            }
        }
        // Fused epilogue for plane k
        float BgK = Bg[k], Uk = U[k];
        float p1L = g_P1[((size_t)bbv * Ll + iL) * Ss + k] + BgK;
        float p1H = g_P1[((size_t)bbv * Ll + iH) * Ss + k] + BgK;
        float q1L = g_Q1[((size_t)bbv * Ll + iL) * Ss + k];
        float q1H = g_Q1[((size_t)bbv * Ll + iH) * Ss + k];
        const float* p2b = g_P2t + ((size_t)(bbv * 8 + k)) * Ll + j0 + wj * 32;
        const float* q2b = g_Q2t + ((size_t)(bbv * 8 + k)) * Ll + j0 + wj * 32;
#pragma unroll
        for (int nt = 0; nt < 4; nt++)
#pragma unroll
            for (int e = 0; e < 2; e++) {
                int jc = nt * 8 + (lane & 3) * 2 + e;
                float p2 = p2b[jc], q2 = q2b[jc];
                float gL = sig_fma(p1L + p2), sL = sig_fma(q1L + q2);
                float gH = sig_fma(p1H + p2), sH = sig_fma(q1H + q2);
                float bL = accH[nt][e] + accL[nt][e];
                float bH = accH[nt][2 + e] + accL[nt][2 + e];
                sc[nt][0][e] += Uk * fmaf(bL - sL, gL, sL);
                sc[nt][1][e] += Uk * fmaf(bH - sH, gH, sH);
            }
    }

    // Final sigmoid + store
#pragma unroll
    for (int nt = 0; nt < 4; nt++) {
        int jc = j0 + wj * 32 + nt * 8 + (lane & 3) * 2;
        float2 v0 = make_float2(sig_fma(sc[nt][0][0]), sig_fma(sc[nt][0][1]));
        float2 v1 = make_float2(sig_fma(sc[nt][1][0]), sig_fma(sc[nt][1][1]));
        *reinterpret_cast<float2*>(&out[((size_t)bbv * Ll + iL) * Ll + jc]) = v0;
        *reinterpret_cast<float2*>(&out[((size_t)bbv * Ll + iH) * Ll + jc]) = v1;
    }
}

// ---------------------------------------------------------------------------
extern "C" void kernel_launch(void* const* d_in, const int* in_sizes, int n_in,
                              void* d_out, int out_size) {
    const float* arg1 = (const float*)d_in[0];
    const float* arg2 = (const float*)d_in[1];
    const float* Wg   = (const float*)d_in[2];
    const float* Bg   = (const float*)d_in[3];
    const float* Mr   = (const float*)d_in[4];
    const float* V    = (const float*)d_in[5];
    const float* bvec = (const float*)d_in[6];
    const float* U    = (const float*)d_in[7];
    float* out = (float*)d_out;

    cudaFuncSetAttribute(gemm1_kernel, cudaFuncAttributeMaxDynamicSharedMemorySize, S1_SMEM);
    cudaFuncSetAttribute(gemm2_kernel, cudaFuncAttributeMaxDynamicSharedMemorySize, S2_SMEM);

    mrsplit_kernel<<<(Ss * Dd * Dd) / 1024, 256>>>(Mr);
    conv_proj_kernel<<<(2 * Bb * Ll) / 8, 256>>>(arg1, arg2, Wg, V);

    dim3 g1(Dd / 128, Ll / 128, Bb * Ss);
    gemm1_kernel<<<g1, 512, S1_SMEM>>>();

    dim3 g2(Ll / 128, Ll / 64, Bb);
    gemm2_kernel<<<g2, 512, S2_SMEM>>>(Bg, bvec, U, out);
}

// round 10
// speedup vs baseline: 1.5705x; 1.5705x over previous
#include <cuda_runtime.h>
#include <cuda_bf16.h>
#include <cstdint>

#define Bb 32
#define Ll 512
#define Dd 512
#define Ss 8

// ---------------------------------------------------------------------------
// Device-global scratch
// ---------------------------------------------------------------------------
__device__ __nv_bfloat16 g_A2hi[(size_t)Bb * Ss * Ll * Dd];
__device__ __nv_bfloat16 g_A2lo[(size_t)Bb * Ss * Ll * Dd];
__device__ __nv_bfloat16 g_A1hi[(size_t)Bb * Ll * Dd];
__device__ __nv_bfloat16 g_A1lo[(size_t)Bb * Ll * Dd];
__device__ __nv_bfloat16 g_B2hi[(size_t)Bb * Ll * Dd];
__device__ __nv_bfloat16 g_B2lo[(size_t)Bb * Ll * Dd];
__device__ __nv_bfloat16 g_Mrhi[(size_t)Ss * Dd * Dd];
__device__ __nv_bfloat16 g_Mrlo[(size_t)Ss * Dd * Dd];
__device__ float g_P1[Bb * Ll * Ss];
__device__ float g_Q1[Bb * Ll * Ss];
__device__ float g_P2t[Bb * Ss * Ll];
__device__ float g_Q2t[Bb * Ss * Ll];

// ---------------------------------------------------------------------------
// Helpers
// ---------------------------------------------------------------------------
__device__ __forceinline__ uint32_t smem_u32(const void* p) {
    uint32_t a;
    asm("{ .reg .u64 t; cvta.to.shared.u64 t, %1; cvt.u32.u64 %0, t; }"
        : "=r"(a) : "l"(p));
    return a;
}
__device__ __forceinline__ void ldsm4(uint32_t* r, uint32_t a) {
    asm volatile("ldmatrix.sync.aligned.m8n8.x4.shared.b16 {%0,%1,%2,%3}, [%4];"
                 : "=r"(r[0]), "=r"(r[1]), "=r"(r[2]), "=r"(r[3]) : "r"(a) : "memory");
}
__device__ __forceinline__ void mma_bf16(float* c, const uint32_t* a, const uint32_t* b) {
    asm volatile("mma.sync.aligned.m16n8k16.row.col.f32.bf16.bf16.f32 "
                 "{%0,%1,%2,%3}, {%4,%5,%6,%7}, {%8,%9}, {%0,%1,%2,%3};"
                 : "+f"(c[0]), "+f"(c[1]), "+f"(c[2]), "+f"(c[3])
                 : "r"(a[0]), "r"(a[1]), "r"(a[2]), "r"(a[3]), "r"(b[0]), "r"(b[1]));
}
#define CP16(dst, src) \
    asm volatile("cp.async.cg.shared.global [%0], [%1], 16;" :: "r"(dst), "l"(src) : "memory")
#define CPCOMMIT() asm volatile("cp.async.commit_group;" ::: "memory")
#define CPWAIT1() asm volatile("cp.async.wait_group 1;" ::: "memory")

__device__ __forceinline__ uint32_t pack_bf16x2(float a, float b) {
    uint32_t h;
    asm("cvt.rn.bf16x2.f32 %0, %1, %2;" : "=r"(h) : "f"(b), "f"(a));
    return h;
}
__device__ __forceinline__ void split2(float a, float b, uint32_t& h, uint32_t& l) {
    h = pack_bf16x2(a, b);
    float ha = __uint_as_float(h << 16), hb = __uint_as_float(h & 0xFFFF0000u);
    l = pack_bf16x2(a - ha, b - hb);
}

// FMA-pipe-only sigmoid, abs err ~1.5e-5
__device__ __forceinline__ float sig_fma(float x) {
    float ax = fminf(fabsf(x), 20.0f);
    float y = -1.44269504f * ax;
    float t = y + 12582912.0f;
    int n = __float_as_int(t) - 0x4B400000;
    float f = y - (t - 12582912.0f);
    float p = 1.33335581e-3f;
    p = fmaf(p, f, 9.61812910e-3f);
    p = fmaf(p, f, 5.55041086e-2f);
    p = fmaf(p, f, 2.40226507e-1f);
    p = fmaf(p, f, 6.93147181e-1f);
    p = fmaf(p, f, 1.0f);
    float E = __int_as_float(__float_as_int(p) + (n << 23));
    float w = 1.0f + E;
    float r = __int_as_float(0x7EF127EAu - __float_as_int(w));
    r = r * (2.0f - w * r);
    r = r * (2.0f - w * r);
    return x >= 0.0f ? r : 1.0f - r;
}

// ---------------------------------------------------------------------------
// K0: split Mr into bf16 hi/lo
// ---------------------------------------------------------------------------
__global__ void mrsplit_kernel(const float* __restrict__ Mr) {
    size_t i = ((size_t)blockIdx.x * 256 + threadIdx.x) * 4;
    float4 v = *reinterpret_cast<const float4*>(Mr + i);
    uint32_t h0, l0, h1, l1;
    split2(v.x, v.y, h0, l0);
    split2(v.z, v.w, h1, l1);
    *reinterpret_cast<uint2*>(&g_Mrhi[i]) = make_uint2(h0, h1);
    *reinterpret_cast<uint2*>(&g_Mrlo[i]) = make_uint2(l0, l1);
}

// ---------------------------------------------------------------------------
// K1: fused projections + input split. One warp per row.
// ---------------------------------------------------------------------------
__global__ void conv_proj_kernel(const float* __restrict__ arg1,
                                 const float* __restrict__ arg2,
                                 const float* __restrict__ Wg,
                                 const float* __restrict__ V) {
    int w = (blockIdx.x * blockDim.x + threadIdx.x) >> 5;
    int lane = threadIdx.x & 31;
    bool first = (w < Bb * Ll);
    const float* src = first ? arg1 : arg2;
    int row = first ? w : w - Bb * Ll;
    int woff = first ? 0 : Dd;
    __nv_bfloat16* dh = first ? g_A1hi : g_B2hi;
    __nv_bfloat16* dl = first ? g_A1lo : g_B2lo;

    float aw[8] = {0,0,0,0,0,0,0,0}, av[8] = {0,0,0,0,0,0,0,0};
    const float* srow = src + (size_t)row * Dd;
#pragma unroll
    for (int q = 0; q < 4; q++) {
        int d0 = (q * 32 + lane) * 4;
        float4 x = *reinterpret_cast<const float4*>(srow + d0);
        uint32_t h0, l0, h1, l1;
        split2(x.x, x.y, h0, l0);
        split2(x.z, x.w, h1, l1);
        *reinterpret_cast<uint2*>(&dh[(size_t)row * Dd + d0]) = make_uint2(h0, h1);
        *reinterpret_cast<uint2*>(&dl[(size_t)row * Dd + d0]) = make_uint2(l0, l1);
        float xs[4] = {x.x, x.y, x.z, x.w};
#pragma unroll
        for (int e = 0; e < 4; e++) {
            int d = d0 + e;
            const float4* wp = reinterpret_cast<const float4*>(Wg + (size_t)(woff + d) * Ss);
            const float4* vp = reinterpret_cast<const float4*>(V  + (size_t)(woff + d) * Ss);
            float4 w0 = wp[0], w1 = wp[1], v0 = vp[0], v1 = vp[1];
            float xv = xs[e];
            aw[0] += xv*w0.x; aw[1] += xv*w0.y; aw[2] += xv*w0.z; aw[3] += xv*w0.w;
            aw[4] += xv*w1.x; aw[5] += xv*w1.y; aw[6] += xv*w1.z; aw[7] += xv*w1.w;
            av[0] += xv*v0.x; av[1] += xv*v0.y; av[2] += xv*v0.z; av[3] += xv*v0.w;
            av[4] += xv*v1.x; av[5] += xv*v1.y; av[6] += xv*v1.z; av[7] += xv*v1.w;
        }
    }
#pragma unroll
    for (int s = 0; s < 8; s++)
#pragma unroll
        for (int o = 16; o > 0; o >>= 1) {
            aw[s] += __shfl_xor_sync(0xffffffffu, aw[s], o);
            av[s] += __shfl_xor_sync(0xffffffffu, av[s], o);
        }
    if (lane == 0) {
        if (first) {
#pragma unroll
            for (int s = 0; s < 8; s++) {
                g_P1[(size_t)row * Ss + s] = aw[s];
                g_Q1[(size_t)row * Ss + s] = av[s];
            }
        } else {
            int bbv = row >> 9, j = row & 511;
#pragma unroll
            for (int s = 0; s < 8; s++) {
                g_P2t[((size_t)bbv * Ss + s) * Ll + j] = aw[s];
                g_Q2t[((size_t)bbv * Ss + s) * Ll + j] = av[s];
            }
        }
    }
}

// ---------------------------------------------------------------------------
// K2: A2 = arg2 @ Mr^T, 3-pass. CTA 128x128, 512 thr (16 warps, 32m x 32n),
// K-chunk 64, 3-stage cp.async. (R7-verbatim)
// ---------------------------------------------------------------------------
#define S1_OP   18432
#define S1_BUF  (4 * S1_OP)
#define S1_SMEM (3 * S1_BUF)

__global__ __launch_bounds__(512, 1) void gemm1_kernel() {
    extern __shared__ char smem[];
    uint32_t sb = smem_u32(smem);
    int t = threadIdx.x, lane = t & 31, wid = t >> 5;
    int bz = blockIdx.z, bbv = bz >> 3, kk = bz & 7;
    int j0 = blockIdx.y * 128, d0 = blockIdx.x * 128;
    int wm = wid & 3, wn = wid >> 2;

    const __nv_bfloat16* srcOp[4] = {
        g_B2hi + ((size_t)bbv * Ll + j0) * Dd,
        g_B2lo + ((size_t)bbv * Ll + j0) * Dd,
        g_Mrhi + ((size_t)kk * Dd + d0) * Dd,
        g_Mrlo + ((size_t)kk * Dd + d0) * Dd};

    int r0 = t >> 3, s0 = t & 7;
    int r1 = (512 + t) >> 3;
    size_t gOff0 = (size_t)r0 * Dd + s0 * 8;
    size_t gOff1 = (size_t)r1 * Dd + s0 * 8;
    uint32_t sOff0 = (uint32_t)(r0 * 144 + s0 * 16);
    uint32_t sOff1 = (uint32_t)(r1 * 144 + s0 * 16);

    auto issue = [&](int c) {
        uint32_t dstb = sb + (c % 3) * S1_BUF;
        int e0 = c * 64;
#pragma unroll
        for (int op = 0; op < 4; op++) {
            CP16(dstb + op * S1_OP + sOff0, srcOp[op] + gOff0 + e0);
            CP16(dstb + op * S1_OP + sOff1, srcOp[op] + gOff1 + e0);
        }
        CPCOMMIT();
    };

    uint32_t aBase[2], bBase[2];
#pragma unroll
    for (int mt = 0; mt < 2; mt++)
        aBase[mt] = (uint32_t)((wm * 32 + mt * 16 + (lane & 15)) * 144 + (lane >> 4) * 16);
#pragma unroll
    for (int nt = 0; nt < 2; nt++)
        bBase[nt] = (uint32_t)((wn * 32 + nt * 16 + (lane & 15)) * 144 + (lane >> 4) * 16);

    float acc[2][4][4];
#pragma unroll
    for (int mt = 0; mt < 2; mt++)
#pragma unroll
        for (int n8 = 0; n8 < 4; n8++)
#pragma unroll
            for (int q = 0; q < 4; q++) acc[mt][n8][q] = 0.f;

    issue(0); issue(1);
#pragma unroll 1
    for (int c = 0; c < 8; c++) {
        if (c < 7) CPWAIT1(); else asm volatile("cp.async.wait_group 0;" ::: "memory");
        __syncthreads();
        if (c < 6) issue(c + 2);
        uint32_t bufb = sb + (c % 3) * S1_BUF;
#pragma unroll
        for (int k16 = 0; k16 < 4; k16++) {
            uint32_t kadd = (uint32_t)(k16 * 32);
            uint32_t ahi[2][4], alo[2][4], bhi[2][4], blo[2][4];
#pragma unroll
            for (int mt = 0; mt < 2; mt++) {
                ldsm4(ahi[mt], bufb + aBase[mt] + kadd);
                ldsm4(alo[mt], bufb + S1_OP + aBase[mt] + kadd);
            }
#pragma unroll
            for (int nt = 0; nt < 2; nt++) {
                ldsm4(bhi[nt], bufb + 2 * S1_OP + bBase[nt] + kadd);
                ldsm4(blo[nt], bufb + 3 * S1_OP + bBase[nt] + kadd);
            }
#pragma unroll
            for (int mt = 0; mt < 2; mt++)
#pragma unroll
                for (int n8 = 0; n8 < 4; n8++) {
                    uint32_t bh[2] = {bhi[n8 >> 1][n8 & 1], bhi[n8 >> 1][(n8 & 1) + 2]};
                    uint32_t bl[2] = {blo[n8 >> 1][n8 & 1], blo[n8 >> 1][(n8 & 1) + 2]};
                    mma_bf16(acc[mt][n8], ahi[mt], bh);
                    mma_bf16(acc[mt][n8], ahi[mt], bl);
                    mma_bf16(acc[mt][n8], alo[mt], bh);
                }
        }
        __syncthreads();
    }

    size_t plane = (size_t)bz * Ll * Dd;
#pragma unroll
    for (int mt = 0; mt < 2; mt++) {
        int jr = j0 + wm * 32 + mt * 16 + (lane >> 2);
#pragma unroll
        for (int n8 = 0; n8 < 4; n8++) {
            int dc = d0 + wn * 32 + n8 * 8 + (lane & 3) * 2;
            size_t x0 = plane + (size_t)jr * Dd + dc;
            size_t x1 = x0 + (size_t)8 * Dd;
            uint32_t h, l;
            split2(acc[mt][n8][0], acc[mt][n8][1], h, l);
            *reinterpret_cast<uint32_t*>(&g_A2hi[x0]) = h;
            *reinterpret_cast<uint32_t*>(&g_A2lo[x0]) = l;
            split2(acc[mt][n8][2], acc[mt][n8][3], h, l);
            *reinterpret_cast<uint32_t*>(&g_A2hi[x1]) = h;
            *reinterpret_cast<uint32_t*>(&g_A2lo[x1]) = l;
        }
    }
}

// ---------------------------------------------------------------------------
// K3: bi = arg1 @ A2^T (8 planes) + fused epilogue. gemm1-clone structure:
// CTA 128i x 128j, 16 warps (4x4) of 32i x 32j, K-chunk 64, 3-stage cp.async,
// A (arg1) re-streamed per plane, B = A2 plane k. m = k*8+c global chunk idx.
// ---------------------------------------------------------------------------
#define S2_OP   18432
#define S2_BUF  (4 * S2_OP)
#define S2_SMEM (3 * S2_BUF)

__global__ __launch_bounds__(512, 1) void gemm2_kernel(const float* __restrict__ Bg,
                                                       const float* __restrict__ bvec,
                                                       const float* __restrict__ U,
                                                       float* __restrict__ out) {
    extern __shared__ char smem[];
    uint32_t sb = smem_u32(smem);
    int t = threadIdx.x, lane = t & 31, wid = t >> 5;
    int bbv = blockIdx.z, i0 = blockIdx.y * 128, j0 = blockIdx.x * 128;
    int wi = wid & 3, wj = wid >> 2;

    const __nv_bfloat16* aHi = g_A1hi + ((size_t)bbv * Ll + i0) * Dd;
    const __nv_bfloat16* aLo = g_A1lo + ((size_t)bbv * Ll + i0) * Dd;
    const __nv_bfloat16* bHi = g_A2hi + ((size_t)bbv * 8 * Ll + j0) * Dd;
    const __nv_bfloat16* bLo = g_A2lo + ((size_t)bbv * 8 * Ll + j0) * Dd;

    int r0 = t >> 3, s0 = t & 7;
    int r1 = (512 + t) >> 3;
    size_t gOff0 = (size_t)r0 * Dd + s0 * 8;
    size_t gOff1 = (size_t)r1 * Dd + s0 * 8;
    uint32_t sOff0 = (uint32_t)(r0 * 144 + s0 * 16);
    uint32_t sOff1 = (uint32_t)(r1 * 144 + s0 * 16);

    auto issue = [&](int m) {
        int k = m >> 3;
        int e0 = (m & 7) * 64;
        uint32_t dstb = sb + (m % 3) * S2_BUF;
        size_t pk = (size_t)k * Ll * Dd + e0;
        CP16(dstb + 0 * S2_OP + sOff0, aHi + gOff0 + e0);
        CP16(dstb + 0 * S2_OP + sOff1, aHi + gOff1 + e0);
        CP16(dstb + 1 * S2_OP + sOff0, aLo + gOff0 + e0);
        CP16(dstb + 1 * S2_OP + sOff1, aLo + gOff1 + e0);
        CP16(dstb + 2 * S2_OP + sOff0, bHi + pk + gOff0);
        CP16(dstb + 2 * S2_OP + sOff1, bHi + pk + gOff1);
        CP16(dstb + 3 * S2_OP + sOff0, bLo + pk + gOff0);
        CP16(dstb + 3 * S2_OP + sOff1, bLo + pk + gOff1);
        CPCOMMIT();
    };

    uint32_t aBase[2], bBase[2];
#pragma unroll
    for (int mt = 0; mt < 2; mt++)
        aBase[mt] = (uint32_t)((wi * 32 + mt * 16 + (lane & 15)) * 144 + (lane >> 4) * 16);
#pragma unroll
    for (int nt = 0; nt < 2; nt++)
        bBase[nt] = (uint32_t)((wj * 32 + nt * 16 + (lane & 15)) * 144 + (lane >> 4) * 16);

    float bU = 0.f;
#pragma unroll
    for (int s = 0; s < 8; s++) bU += bvec[s] * U[s];

    float acc[2][4][4], sc[2][4][4];
#pragma unroll
    for (int mt = 0; mt < 2; mt++)
#pragma unroll
        for (int n8 = 0; n8 < 4; n8++)
#pragma unroll
            for (int q = 0; q < 4; q++) { acc[mt][n8][q] = 0.f; sc[mt][n8][q] = bU; }

    issue(0); issue(1);
#pragma unroll 1
    for (int m = 0; m < 64; m++) {
        CPWAIT1();
        __syncthreads();
        if (m < 62) issue(m + 2); else CPCOMMIT();
        uint32_t bufb = sb + (m % 3) * S2_BUF;
#pragma unroll
        for (int k16 = 0; k16 < 4; k16++) {
            uint32_t kadd = (uint32_t)(k16 * 32);
            uint32_t ahi[2][4], alo[2][4], bhi[2][4], blo[2][4];
#pragma unroll
            for (int mt = 0; mt < 2; mt++) {
                ldsm4(ahi[mt], bufb + aBase[mt] + kadd);
                ldsm4(alo[mt], bufb + S2_OP + aBase[mt] + kadd);
            }
#pragma unroll
            for (int nt = 0; nt < 2; nt++) {
                ldsm4(bhi[nt], bufb + 2 * S2_OP + bBase[nt] + kadd);
                ldsm4(blo[nt], bufb + 3 * S2_OP + bBase[nt] + kadd);
            }
            // pass-major: same-acc RAW spaced 8 MMAs apart
#pragma unroll
            for (int mt = 0; mt < 2; mt++)
#pragma unroll
                for (int n8 = 0; n8 < 4; n8++) {
                    uint32_t bh[2] = {bhi[n8 >> 1][n8 & 1], bhi[n8 >> 1][(n8 & 1) + 2]};
                    mma_bf16(acc[mt][n8], ahi[mt], bh);
                }
#pragma unroll
            for (int mt = 0; mt < 2; mt++)
#pragma unroll
                for (int n8 = 0; n8 < 4; n8++) {
                    uint32_t bl[2] = {blo[n8 >> 1][n8 & 1], blo[n8 >> 1][(n8 & 1) + 2]};
                    mma_bf16(acc[mt][n8], ahi[mt], bl);
                }
#pragma unroll
            for (int mt = 0; mt < 2; mt++)
#pragma unroll
                for (int n8 = 0; n8 < 4; n8++) {
                    uint32_t bh[2] = {bhi[n8 >> 1][n8 & 1], bhi[n8 >> 1][(n8 & 1) + 2]};
                    mma_bf16(acc[mt][n8], alo[mt], bh);
                }
        }
        __syncthreads();

        if ((m & 7) == 7) {
            // plane k complete: fused gated epilogue into sc, reset acc
            int k = m >> 3;
            float BgK = Bg[k], Uk = U[k];
            const float* p2b = g_P2t + ((size_t)(bbv * 8 + k)) * Ll + j0 + wj * 32;
            const float* q2b = g_Q2t + ((size_t)(bbv * 8 + k)) * Ll + j0 + wj * 32;
#pragma unroll
            for (int mt = 0; mt < 2; mt++) {
                int iL = i0 + wi * 32 + mt * 16 + (lane >> 2);
                int iH = iL + 8;
                float p1L = g_P1[((size_t)bbv * Ll + iL) * Ss + k] + BgK;
                float p1H = g_P1[((size_t)bbv * Ll + iH) * Ss + k] + BgK;
                float q1L = g_Q1[((size_t)bbv * Ll + iL) * Ss + k];
                float q1H = g_Q1[((size_t)bbv * Ll + iH) * Ss + k];
#pragma unroll
                for (int n8 = 0; n8 < 4; n8++)
#pragma unroll
                    for (int e = 0; e < 2; e++) {
                        int jc = n8 * 8 + (lane & 3) * 2 + e;
                        float p2 = p2b[jc], q2 = q2b[jc];
                        float gL = sig_fma(p1L + p2), sL = sig_fma(q1L + q2);
                        float gH = sig_fma(p1H + p2), sH = sig_fma(q1H + q2);
                        sc[mt][n8][e]     += Uk * fmaf(acc[mt][n8][e] - sL, gL, sL);
                        sc[mt][n8][2 + e] += Uk * fmaf(acc[mt][n8][2 + e] - sH, gH, sH);
                        acc[mt][n8][e] = 0.f;
                        acc[mt][n8][2 + e] = 0.f;
                    }
            }
        }
    }

    // Final sigmoid + store
#pragma unroll
    for (int mt = 0; mt < 2; mt++) {
        int iL = i0 + wi * 32 + mt * 16 + (lane >> 2);
        int iH = iL + 8;
#pragma unroll
        for (int n8 = 0; n8 < 4; n8++) {
            int jc = j0 + wj * 32 + n8 * 8 + (lane & 3) * 2;
            float2 v0 = make_float2(sig_fma(sc[mt][n8][0]), sig_fma(sc[mt][n8][1]));
            float2 v1 = make_float2(sig_fma(sc[mt][n8][2]), sig_fma(sc[mt][n8][3]));
            *reinterpret_cast<float2*>(&out[((size_t)bbv * Ll + iL) * Ll + jc]) = v0;
            *reinterpret_cast<float2*>(&out[((size_t)bbv * Ll + iH) * Ll + jc]) = v1;
        }
    }
}

// ---------------------------------------------------------------------------
extern "C" void kernel_launch(void* const* d_in, const int* in_sizes, int n_in,
                              void* d_out, int out_size) {
    const float* arg1 = (const float*)d_in[0];
    const float* arg2 = (const float*)d_in[1];
    const float* Wg   = (const float*)d_in[2];
    const float* Bg   = (const float*)d_in[3];
    const float* Mr   = (const float*)d_in[4];
    const float* V    = (const float*)d_in[5];
    const float* bvec = (const float*)d_in[6];
    const float* U    = (const float*)d_in[7];
    float* out = (float*)d_out;

    cudaFuncSetAttribute(gemm1_kernel, cudaFuncAttributeMaxDynamicSharedMemorySize, S1_SMEM);
    cudaFuncSetAttribute(gemm2_kernel, cudaFuncAttributeMaxDynamicSharedMemorySize, S2_SMEM);

    mrsplit_kernel<<<(Ss * Dd * Dd) / 1024, 256>>>(Mr);
    conv_proj_kernel<<<(2 * Bb * Ll) / 8, 256>>>(arg1, arg2, Wg, V);

    dim3 g1(Dd / 128, Ll / 128, Bb * Ss);
    gemm1_kernel<<<g1, 512, S1_SMEM>>>();

    dim3 g2(Ll / 128, Ll / 128, Bb);
    gemm2_kernel<<<g2, 512, S2_SMEM>>>(Bg, bvec, U, out);
}

// round 11
// speedup vs baseline: 1.7093x; 1.0883x over previous
#include <cuda_runtime.h>
#include <cuda_bf16.h>
#include <cstdint>

#define Bb 32
#define Ll 512
#define Dd 512
#define Ss 8

// ---------------------------------------------------------------------------
// Device-global scratch
// ---------------------------------------------------------------------------
__device__ __nv_bfloat16 g_A2hi[(size_t)Bb * Ss * Ll * Dd];
__device__ __nv_bfloat16 g_A2lo[(size_t)Bb * Ss * Ll * Dd];
__device__ __nv_bfloat16 g_A1hi[(size_t)Bb * Ll * Dd];
__device__ __nv_bfloat16 g_A1lo[(size_t)Bb * Ll * Dd];
__device__ __nv_bfloat16 g_B2hi[(size_t)Bb * Ll * Dd];
__device__ __nv_bfloat16 g_B2lo[(size_t)Bb * Ll * Dd];
__device__ __nv_bfloat16 g_Mrhi[(size_t)Ss * Dd * Dd];
__device__ __nv_bfloat16 g_Mrlo[(size_t)Ss * Dd * Dd];
__device__ float g_P1[Bb * Ll * Ss];
__device__ float g_Q1[Bb * Ll * Ss];
__device__ float g_P2t[Bb * Ss * Ll];
__device__ float g_Q2t[Bb * Ss * Ll];

// ---------------------------------------------------------------------------
// Helpers
// ---------------------------------------------------------------------------
__device__ __forceinline__ uint32_t smem_u32(const void* p) {
    uint32_t a;
    asm("{ .reg .u64 t; cvta.to.shared.u64 t, %1; cvt.u32.u64 %0, t; }"
        : "=r"(a) : "l"(p));
    return a;
}
__device__ __forceinline__ void ldsm4(uint32_t* r, uint32_t a) {
    asm volatile("ldmatrix.sync.aligned.m8n8.x4.shared.b16 {%0,%1,%2,%3}, [%4];"
                 : "=r"(r[0]), "=r"(r[1]), "=r"(r[2]), "=r"(r[3]) : "r"(a) : "memory");
}
__device__ __forceinline__ void mma_bf16(float* c, const uint32_t* a, const uint32_t* b) {
    asm volatile("mma.sync.aligned.m16n8k16.row.col.f32.bf16.bf16.f32 "
                 "{%0,%1,%2,%3}, {%4,%5,%6,%7}, {%8,%9}, {%0,%1,%2,%3};"
                 : "+f"(c[0]), "+f"(c[1]), "+f"(c[2]), "+f"(c[3])
                 : "r"(a[0]), "r"(a[1]), "r"(a[2]), "r"(a[3]), "r"(b[0]), "r"(b[1]));
}
#define CP16(dst, src) \
    asm volatile("cp.async.cg.shared.global [%0], [%1], 16;" :: "r"(dst), "l"(src) : "memory")
#define CPCOMMIT() asm volatile("cp.async.commit_group;" ::: "memory")
#define CPWAIT1() asm volatile("cp.async.wait_group 1;" ::: "memory")

__device__ __forceinline__ uint32_t pack_bf16x2(float a, float b) {
    uint32_t h;
    asm("cvt.rn.bf16x2.f32 %0, %1, %2;" : "=r"(h) : "f"(b), "f"(a));
    return h;
}
__device__ __forceinline__ void split2(float a, float b, uint32_t& h, uint32_t& l) {
    h = pack_bf16x2(a, b);
    float ha = __uint_as_float(h << 16), hb = __uint_as_float(h & 0xFFFF0000u);
    l = pack_bf16x2(a - ha, b - hb);
}

// FMA-pipe-only sigmoid, abs err ~1.5e-5
__device__ __forceinline__ float sig_fma(float x) {
    float ax = fminf(fabsf(x), 20.0f);
    float y = -1.44269504f * ax;
    float t = y + 12582912.0f;
    int n = __float_as_int(t) - 0x4B400000;
    float f = y - (t - 12582912.0f);
    float p = 1.33335581e-3f;
    p = fmaf(p, f, 9.61812910e-3f);
    p = fmaf(p, f, 5.55041086e-2f);
    p = fmaf(p, f, 2.40226507e-1f);
    p = fmaf(p, f, 6.93147181e-1f);
    p = fmaf(p, f, 1.0f);
    float E = __int_as_float(__float_as_int(p) + (n << 23));
    float w = 1.0f + E;
    float r = __int_as_float(0x7EF127EAu - __float_as_int(w));
    r = r * (2.0f - w * r);
    r = r * (2.0f - w * r);
    return x >= 0.0f ? r : 1.0f - r;
}

// ---------------------------------------------------------------------------
// K0: split Mr into bf16 hi/lo
// ---------------------------------------------------------------------------
__global__ void mrsplit_kernel(const float* __restrict__ Mr) {
    size_t i = ((size_t)blockIdx.x * 256 + threadIdx.x) * 4;
    float4 v = *reinterpret_cast<const float4*>(Mr + i);
    uint32_t h0, l0, h1, l1;
    split2(v.x, v.y, h0, l0);
    split2(v.z, v.w, h1, l1);
    *reinterpret_cast<uint2*>(&g_Mrhi[i]) = make_uint2(h0, h1);
    *reinterpret_cast<uint2*>(&g_Mrlo[i]) = make_uint2(l0, l1);
}

// ---------------------------------------------------------------------------
// K1: fused projections + input split. One warp per row.
// ---------------------------------------------------------------------------
__global__ void conv_proj_kernel(const float* __restrict__ arg1,
                                 const float* __restrict__ arg2,
                                 const float* __restrict__ Wg,
                                 const float* __restrict__ V) {
    int w = (blockIdx.x * blockDim.x + threadIdx.x) >> 5;
    int lane = threadIdx.x & 31;
    bool first = (w < Bb * Ll);
    const float* src = first ? arg1 : arg2;
    int row = first ? w : w - Bb * Ll;
    int woff = first ? 0 : Dd;
    __nv_bfloat16* dh = first ? g_A1hi : g_B2hi;
    __nv_bfloat16* dl = first ? g_A1lo : g_B2lo;

    float aw[8] = {0,0,0,0,0,0,0,0}, av[8] = {0,0,0,0,0,0,0,0};
    const float* srow = src + (size_t)row * Dd;
#pragma unroll
    for (int q = 0; q < 4; q++) {
        int d0 = (q * 32 + lane) * 4;
        float4 x = *reinterpret_cast<const float4*>(srow + d0);
        uint32_t h0, l0, h1, l1;
        split2(x.x, x.y, h0, l0);
        split2(x.z, x.w, h1, l1);
        *reinterpret_cast<uint2*>(&dh[(size_t)row * Dd + d0]) = make_uint2(h0, h1);
        *reinterpret_cast<uint2*>(&dl[(size_t)row * Dd + d0]) = make_uint2(l0, l1);
        float xs[4] = {x.x, x.y, x.z, x.w};
#pragma unroll
        for (int e = 0; e < 4; e++) {
            int d = d0 + e;
            const float4* wp = reinterpret_cast<const float4*>(Wg + (size_t)(woff + d) * Ss);
            const float4* vp = reinterpret_cast<const float4*>(V  + (size_t)(woff + d) * Ss);
            float4 w0 = wp[0], w1 = wp[1], v0 = vp[0], v1 = vp[1];
            float xv = xs[e];
            aw[0] += xv*w0.x; aw[1] += xv*w0.y; aw[2] += xv*w0.z; aw[3] += xv*w0.w;
            aw[4] += xv*w1.x; aw[5] += xv*w1.y; aw[6] += xv*w1.z; aw[7] += xv*w1.w;
            av[0] += xv*v0.x; av[1] += xv*v0.y; av[2] += xv*v0.z; av[3] += xv*v0.w;
            av[4] += xv*v1.x; av[5] += xv*v1.y; av[6] += xv*v1.z; av[7] += xv*v1.w;
        }
    }
#pragma unroll
    for (int s = 0; s < 8; s++)
#pragma unroll
        for (int o = 16; o > 0; o >>= 1) {
            aw[s] += __shfl_xor_sync(0xffffffffu, aw[s], o);
            av[s] += __shfl_xor_sync(0xffffffffu, av[s], o);
        }
    if (lane == 0) {
        if (first) {
#pragma unroll
            for (int s = 0; s < 8; s++) {
                g_P1[(size_t)row * Ss + s] = aw[s];
                g_Q1[(size_t)row * Ss + s] = av[s];
            }
        } else {
            int bbv = row >> 9, j = row & 511;
#pragma unroll
            for (int s = 0; s < 8; s++) {
                g_P2t[((size_t)bbv * Ss + s) * Ll + j] = aw[s];
                g_Q2t[((size_t)bbv * Ss + s) * Ll + j] = av[s];
            }
        }
    }
}

// ---------------------------------------------------------------------------
// Shared GEMM geometry: CTA 128x128, 512 thr (16 warps, 32m x 32n),
// K-chunk 32, 3-stage cp.async, 2 CTAs/SM.
// SMEM rows: 64B, swizzle seg' = seg ^ ((row>>1)&3)  (conflict-free ldsm+cp).
// Per stage: 4 operand planes (Ahi|Alo|Bhi|Blo) of 128 rows x 64B.
// ---------------------------------------------------------------------------
#define OPB   8192                 // 128 * 64
#define BUFB  (4 * OPB)            // 32768
#define GSMEM (3 * BUFB)           // 98304

// cp.async dst offset for thread t (one 16B seg of one row per op)
__device__ __forceinline__ uint32_t cp_dst(int t) {
    int r = t >> 2, seg = t & 3;
    return (uint32_t)(r * 64 + ((seg ^ ((r >> 1) & 3)) * 16));
}
// ldsm base offset for tile row block at kk=0; kk=1 = offset ^ 32
__device__ __forceinline__ uint32_t ldsm_off(int rowBase, int lane) {
    int row = rowBase + (lane & 15);
    int seg = lane >> 4;                    // 0/1 within k16
    return (uint32_t)(row * 64 + ((seg ^ ((row >> 1) & 3)) * 16));
}

// ---------------------------------------------------------------------------
// K2: A2 = arg2 @ Mr^T, 3-pass.
// ---------------------------------------------------------------------------
__global__ __launch_bounds__(512, 2) void gemm1_kernel() {
    extern __shared__ char smem[];
    uint32_t sb = smem_u32(smem);
    int t = threadIdx.x, lane = t & 31, wid = t >> 5;
    int bz = blockIdx.z, bbv = bz >> 3, kk = bz & 7;
    int j0 = blockIdx.y * 128, d0 = blockIdx.x * 128;
    int wm = wid & 3, wn = wid >> 2;

    const __nv_bfloat16* srcOp[4] = {
        g_B2hi + ((size_t)bbv * Ll + j0) * Dd,
        g_B2lo + ((size_t)bbv * Ll + j0) * Dd,
        g_Mrhi + ((size_t)kk * Dd + d0) * Dd,
        g_Mrlo + ((size_t)kk * Dd + d0) * Dd};

    int rr = t >> 2, sg = t & 3;
    size_t gOff = (size_t)rr * Dd + sg * 8;
    uint32_t dOff = cp_dst(t);

    auto issue = [&](int c) {
        uint32_t dstb = sb + (c % 3) * BUFB;
        int e0 = c * 32;
#pragma unroll
        for (int op = 0; op < 4; op++)
            CP16(dstb + op * OPB + dOff, srcOp[op] + gOff + e0);
        CPCOMMIT();
    };

    uint32_t aB[2], bB[2];
#pragma unroll
    for (int mt = 0; mt < 2; mt++) aB[mt] = ldsm_off(wm * 32 + mt * 16, lane);
#pragma unroll
    for (int nt = 0; nt < 2; nt++) bB[nt] = ldsm_off(wn * 32 + nt * 16, lane);

    float acc[2][4][4];
#pragma unroll
    for (int mt = 0; mt < 2; mt++)
#pragma unroll
        for (int n8 = 0; n8 < 4; n8++)
#pragma unroll
            for (int q = 0; q < 4; q++) acc[mt][n8][q] = 0.f;

    issue(0); issue(1);
#pragma unroll 1
    for (int c = 0; c < 16; c++) {
        CPWAIT1();
        __syncthreads();
        if (c < 14) issue(c + 2); else CPCOMMIT();
        uint32_t bufb = sb + (c % 3) * BUFB;
#pragma unroll
        for (int k16 = 0; k16 < 2; k16++) {
            uint32_t kx = (uint32_t)(k16 * 32);  // swizzled: seg bit1 flip = XOR 32
            uint32_t ahi[2][4], alo[2][4], bhi[2][4], blo[2][4];
#pragma unroll
            for (int mt = 0; mt < 2; mt++) {
                ldsm4(ahi[mt], bufb + (aB[mt] ^ kx));
                ldsm4(alo[mt], bufb + OPB + (aB[mt] ^ kx));
            }
#pragma unroll
            for (int nt = 0; nt < 2; nt++) {
                ldsm4(bhi[nt], bufb + 2 * OPB + (bB[nt] ^ kx));
                ldsm4(blo[nt], bufb + 3 * OPB + (bB[nt] ^ kx));
            }
#pragma unroll
            for (int mt = 0; mt < 2; mt++)
#pragma unroll
                for (int n8 = 0; n8 < 4; n8++) {
                    uint32_t bh[2] = {bhi[n8 >> 1][n8 & 1], bhi[n8 >> 1][(n8 & 1) + 2]};
                    mma_bf16(acc[mt][n8], ahi[mt], bh);
                }
#pragma unroll
            for (int mt = 0; mt < 2; mt++)
#pragma unroll
                for (int n8 = 0; n8 < 4; n8++) {
                    uint32_t bl[2] = {blo[n8 >> 1][n8 & 1], blo[n8 >> 1][(n8 & 1) + 2]};
                    mma_bf16(acc[mt][n8], ahi[mt], bl);
                }
#pragma unroll
            for (int mt = 0; mt < 2; mt++)
#pragma unroll
                for (int n8 = 0; n8 < 4; n8++) {
                    uint32_t bh[2] = {bhi[n8 >> 1][n8 & 1], bhi[n8 >> 1][(n8 & 1) + 2]};
                    mma_bf16(acc[mt][n8], alo[mt], bh);
                }
        }
        __syncthreads();
    }

    size_t plane = (size_t)bz * Ll * Dd;
#pragma unroll
    for (int mt = 0; mt < 2; mt++) {
        int jr = j0 + wm * 32 + mt * 16 + (lane >> 2);
#pragma unroll
        for (int n8 = 0; n8 < 4; n8++) {
            int dc = d0 + wn * 32 + n8 * 8 + (lane & 3) * 2;
            size_t x0 = plane + (size_t)jr * Dd + dc;
            size_t x1 = x0 + (size_t)8 * Dd;
            uint32_t h, l;
            split2(acc[mt][n8][0], acc[mt][n8][1], h, l);
            *reinterpret_cast<uint32_t*>(&g_A2hi[x0]) = h;
            *reinterpret_cast<uint32_t*>(&g_A2lo[x0]) = l;
            split2(acc[mt][n8][2], acc[mt][n8][3], h, l);
            *reinterpret_cast<uint32_t*>(&g_A2hi[x1]) = h;
            *reinterpret_cast<uint32_t*>(&g_A2lo[x1]) = l;
        }
    }
}

// ---------------------------------------------------------------------------
// K3: bi = arg1 @ A2^T (8 planes) + fused epilogue (same geometry).
// m = k*16 + c; plane epilogue at (m&15)==15.
// ---------------------------------------------------------------------------
__global__ __launch_bounds__(512, 2) void gemm2_kernel(const float* __restrict__ Bg,
                                                       const float* __restrict__ bvec,
                                                       const float* __restrict__ U,
                                                       float* __restrict__ out) {
    extern __shared__ char smem[];
    uint32_t sb = smem_u32(smem);
    int t = threadIdx.x, lane = t & 31, wid = t >> 5;
    int bbv = blockIdx.z, i0 = blockIdx.y * 128, j0 = blockIdx.x * 128;
    int wi = wid & 3, wj = wid >> 2;

    const __nv_bfloat16* aHi = g_A1hi + ((size_t)bbv * Ll + i0) * Dd;
    const __nv_bfloat16* aLo = g_A1lo + ((size_t)bbv * Ll + i0) * Dd;
    const __nv_bfloat16* bHi = g_A2hi + ((size_t)bbv * 8 * Ll + j0) * Dd;
    const __nv_bfloat16* bLo = g_A2lo + ((size_t)bbv * 8 * Ll + j0) * Dd;

    int rr = t >> 2, sg = t & 3;
    size_t gOff = (size_t)rr * Dd + sg * 8;
    uint32_t dOff = cp_dst(t);

    auto issue = [&](int m) {
        int k = m >> 4;
        int e0 = (m & 15) * 32;
        uint32_t dstb = sb + (m % 3) * BUFB;
        size_t pk = (size_t)k * Ll * Dd + e0;
        CP16(dstb + 0 * OPB + dOff, aHi + gOff + e0);
        CP16(dstb + 1 * OPB + dOff, aLo + gOff + e0);
        CP16(dstb + 2 * OPB + dOff, bHi + pk + gOff);
        CP16(dstb + 3 * OPB + dOff, bLo + pk + gOff);
        CPCOMMIT();
    };

    uint32_t aB[2], bB[2];
#pragma unroll
    for (int mt = 0; mt < 2; mt++) aB[mt] = ldsm_off(wi * 32 + mt * 16, lane);
#pragma unroll
    for (int nt = 0; nt < 2; nt++) bB[nt] = ldsm_off(wj * 32 + nt * 16, lane);

    float bU = 0.f;
#pragma unroll
    for (int s = 0; s < 8; s++) bU += bvec[s] * U[s];

    float acc[2][4][4], sc[2][4][4];
#pragma unroll
    for (int mt = 0; mt < 2; mt++)
#pragma unroll
        for (int n8 = 0; n8 < 4; n8++)
#pragma unroll
            for (int q = 0; q < 4; q++) { acc[mt][n8][q] = 0.f; sc[mt][n8][q] = bU; }

    issue(0); issue(1);
#pragma unroll 1
    for (int m = 0; m < 128; m++) {
        CPWAIT1();
        __syncthreads();
        if (m < 126) issue(m + 2); else CPCOMMIT();
        uint32_t bufb = sb + (m % 3) * BUFB;
#pragma unroll
        for (int k16 = 0; k16 < 2; k16++) {
            uint32_t kx = (uint32_t)(k16 * 32);
            uint32_t ahi[2][4], alo[2][4], bhi[2][4], blo[2][4];
#pragma unroll
            for (int mt = 0; mt < 2; mt++) {
                ldsm4(ahi[mt], bufb + (aB[mt] ^ kx));
                ldsm4(alo[mt], bufb + OPB + (aB[mt] ^ kx));
            }
#pragma unroll
            for (int nt = 0; nt < 2; nt++) {
                ldsm4(bhi[nt], bufb + 2 * OPB + (bB[nt] ^ kx));
                ldsm4(blo[nt], bufb + 3 * OPB + (bB[nt] ^ kx));
            }
#pragma unroll
            for (int mt = 0; mt < 2; mt++)
#pragma unroll
                for (int n8 = 0; n8 < 4; n8++) {
                    uint32_t bh[2] = {bhi[n8 >> 1][n8 & 1], bhi[n8 >> 1][(n8 & 1) + 2]};
                    mma_bf16(acc[mt][n8], ahi[mt], bh);
                }
#pragma unroll
            for (int mt = 0; mt < 2; mt++)
#pragma unroll
                for (int n8 = 0; n8 < 4; n8++) {
                    uint32_t bl[2] = {blo[n8 >> 1][n8 & 1], blo[n8 >> 1][(n8 & 1) + 2]};
                    mma_bf16(acc[mt][n8], ahi[mt], bl);
                }
#pragma unroll
            for (int mt = 0; mt < 2; mt++)
#pragma unroll
                for (int n8 = 0; n8 < 4; n8++) {
                    uint32_t bh[2] = {bhi[n8 >> 1][n8 & 1], bhi[n8 >> 1][(n8 & 1) + 2]};
                    mma_bf16(acc[mt][n8], alo[mt], bh);
                }
        }
        __syncthreads();

        if ((m & 15) == 15) {
            int k = m >> 4;
            float BgK = Bg[k], Uk = U[k];
            const float* p2b = g_P2t + ((size_t)(bbv * 8 + k)) * Ll + j0 + wj * 32;
            const float* q2b = g_Q2t + ((size_t)(bbv * 8 + k)) * Ll + j0 + wj * 32;
#pragma unroll
            for (int mt = 0; mt < 2; mt++) {
                int iL = i0 + wi * 32 + mt * 16 + (lane >> 2);
                int iH = iL + 8;
                float p1L = g_P1[((size_t)bbv * Ll + iL) * Ss + k] + BgK;
                float p1H = g_P1[((size_t)bbv * Ll + iH) * Ss + k] + BgK;
                float q1L = g_Q1[((size_t)bbv * Ll + iL) * Ss + k];
                float q1H = g_Q1[((size_t)bbv * Ll + iH) * Ss + k];
#pragma unroll
                for (int n8 = 0; n8 < 4; n8++)
#pragma unroll
                    for (int e = 0; e < 2; e++) {
                        int jc = n8 * 8 + (lane & 3) * 2 + e;
                        float p2 = p2b[jc], q2 = q2b[jc];
                        float gL = sig_fma(p1L + p2), sL = sig_fma(q1L + q2);
                        float gH = sig_fma(p1H + p2), sH = sig_fma(q1H + q2);
                        sc[mt][n8][e]     += Uk * fmaf(acc[mt][n8][e] - sL, gL, sL);
                        sc[mt][n8][2 + e] += Uk * fmaf(acc[mt][n8][2 + e] - sH, gH, sH);
                        acc[mt][n8][e] = 0.f;
                        acc[mt][n8][2 + e] = 0.f;
                    }
            }
        }
    }

    // Final sigmoid + store
#pragma unroll
    for (int mt = 0; mt < 2; mt++) {
        int iL = i0 + wi * 32 + mt * 16 + (lane >> 2);
        int iH = iL + 8;
#pragma unroll
        for (int n8 = 0; n8 < 4; n8++) {
            int jc = j0 + wj * 32 + n8 * 8 + (lane & 3) * 2;
            float2 v0 = make_float2(sig_fma(sc[mt][n8][0]), sig_fma(sc[mt][n8][1]));
            float2 v1 = make_float2(sig_fma(sc[mt][n8][2]), sig_fma(sc[mt][n8][3]));
            *reinterpret_cast<float2*>(&out[((size_t)bbv * Ll + iL) * Ll + jc]) = v0;
            *reinterpret_cast<float2*>(&out[((size_t)bbv * Ll + iH) * Ll + jc]) = v1;
        }
    }
}

// ---------------------------------------------------------------------------
extern "C" void kernel_launch(void* const* d_in, const int* in_sizes, int n_in,
                              void* d_out, int out_size) {
    const float* arg1 = (const float*)d_in[0];
    const float* arg2 = (const float*)d_in[1];
    const float* Wg   = (const float*)d_in[2];
    const float* Bg   = (const float*)d_in[3];
    const float* Mr   = (const float*)d_in[4];
    const float* V    = (const float*)d_in[5];
    const float* bvec = (const float*)d_in[6];
    const float* U    = (const float*)d_in[7];
    float* out = (float*)d_out;

    cudaFuncSetAttribute(gemm1_kernel, cudaFuncAttributeMaxDynamicSharedMemorySize, GSMEM);
    cudaFuncSetAttribute(gemm2_kernel, cudaFuncAttributeMaxDynamicSharedMemorySize, GSMEM);

    mrsplit_kernel<<<(Ss * Dd * Dd) / 1024, 256>>>(Mr);
    conv_proj_kernel<<<(2 * Bb * Ll) / 8, 256>>>(arg1, arg2, Wg, V);

    dim3 g1(Dd / 128, Ll / 128, Bb * Ss);
    gemm1_kernel<<<g1, 512, GSMEM>>>();

    dim3 g2(Ll / 128, Ll / 128, Bb);
    gemm2_kernel<<<g2, 512, GSMEM>>>(Bg, bvec, U, out);
}

// round 13
// speedup vs baseline: 1.7588x; 1.0290x over previous
#include <cuda_runtime.h>
#include <cuda_bf16.h>
#include <cstdint>

#define Bb 32
#define Ll 512
#define Dd 512
#define Ss 8

// ---------------------------------------------------------------------------
// Device-global scratch
// ---------------------------------------------------------------------------
__device__ __nv_bfloat16 g_A2hi[(size_t)Bb * Ss * Ll * Dd];
__device__ __nv_bfloat16 g_A2lo[(size_t)Bb * Ss * Ll * Dd];
__device__ __nv_bfloat16 g_A1hi[(size_t)Bb * Ll * Dd];
__device__ __nv_bfloat16 g_A1lo[(size_t)Bb * Ll * Dd];
__device__ __nv_bfloat16 g_B2hi[(size_t)Bb * Ll * Dd];
__device__ __nv_bfloat16 g_B2lo[(size_t)Bb * Ll * Dd];
__device__ __nv_bfloat16 g_Mrhi[(size_t)Ss * Dd * Dd];
__device__ __nv_bfloat16 g_Mrlo[(size_t)Ss * Dd * Dd];
__device__ float g_P1[Bb * Ll * Ss];
__device__ float g_Q1[Bb * Ll * Ss];
__device__ float g_P2t[Bb * Ss * Ll];
__device__ float g_Q2t[Bb * Ss * Ll];

// ---------------------------------------------------------------------------
// Helpers
// ---------------------------------------------------------------------------
__device__ __forceinline__ uint32_t smem_u32(const void* p) {
    uint32_t a;
    asm("{ .reg .u64 t; cvta.to.shared.u64 t, %1; cvt.u32.u64 %0, t; }"
        : "=r"(a) : "l"(p));
    return a;
}
__device__ __forceinline__ void ldsm4(uint32_t* r, uint32_t a) {
    asm volatile("ldmatrix.sync.aligned.m8n8.x4.shared.b16 {%0,%1,%2,%3}, [%4];"
                 : "=r"(r[0]), "=r"(r[1]), "=r"(r[2]), "=r"(r[3]) : "r"(a) : "memory");
}
__device__ __forceinline__ void mma_bf16(float* c, const uint32_t* a, const uint32_t* b) {
    asm volatile("mma.sync.aligned.m16n8k16.row.col.f32.bf16.bf16.f32 "
                 "{%0,%1,%2,%3}, {%4,%5,%6,%7}, {%8,%9}, {%0,%1,%2,%3};"
                 : "+f"(c[0]), "+f"(c[1]), "+f"(c[2]), "+f"(c[3])
                 : "r"(a[0]), "r"(a[1]), "r"(a[2]), "r"(a[3]), "r"(b[0]), "r"(b[1]));
}
#define CP16(dst, src) \
    asm volatile("cp.async.cg.shared.global [%0], [%1], 16;" :: "r"(dst), "l"(src) : "memory")
#define CPCOMMIT() asm volatile("cp.async.commit_group;" ::: "memory")
#define CPWAIT1() asm volatile("cp.async.wait_group 1;" ::: "memory")

__device__ __forceinline__ uint32_t pack_bf16x2(float a, float b) {
    uint32_t h;
    asm("cvt.rn.bf16x2.f32 %0, %1, %2;" : "=r"(h) : "f"(b), "f"(a));
    return h;
}
__device__ __forceinline__ void split2(float a, float b, uint32_t& h, uint32_t& l) {
    h = pack_bf16x2(a, b);
    float ha = __uint_as_float(h << 16), hb = __uint_as_float(h & 0xFFFF0000u);
    l = pack_bf16x2(a - ha, b - hb);
}

// FMA-pipe-only sigmoid, abs err ~1.5e-5
__device__ __forceinline__ float sig_fma(float x) {
    float ax = fminf(fabsf(x), 20.0f);
    float y = -1.44269504f * ax;
    float t = y + 12582912.0f;
    int n = __float_as_int(t) - 0x4B400000;
    float f = y - (t - 12582912.0f);
    float p = 1.33335581e-3f;
    p = fmaf(p, f, 9.61812910e-3f);
    p = fmaf(p, f, 5.55041086e-2f);
    p = fmaf(p, f, 2.40226507e-1f);
    p = fmaf(p, f, 6.93147181e-1f);
    p = fmaf(p, f, 1.0f);
    float E = __int_as_float(__float_as_int(p) + (n << 23));
    float w = 1.0f + E;
    float r = __int_as_float(0x7EF127EAu - __float_as_int(w));
    r = r * (2.0f - w * r);
    r = r * (2.0f - w * r);
    return x >= 0.0f ? r : 1.0f - r;
}

// ---------------------------------------------------------------------------
// K1: fused projections + input split + Mr split (single launch).
// Blocks [0, 4096): proj warps. Blocks [4096, 6144): Mr split.
// ---------------------------------------------------------------------------
__global__ void conv_proj_kernel(const float* __restrict__ arg1,
                                 const float* __restrict__ arg2,
                                 const float* __restrict__ Wg,
                                 const float* __restrict__ V,
                                 const float* __restrict__ Mr) {
    if (blockIdx.x >= 4096) {
        size_t i = ((size_t)(blockIdx.x - 4096) * 256 + threadIdx.x) * 4;
        float4 v = *reinterpret_cast<const float4*>(Mr + i);
        uint32_t h0, l0, h1, l1;
        split2(v.x, v.y, h0, l0);
        split2(v.z, v.w, h1, l1);
        *reinterpret_cast<uint2*>(&g_Mrhi[i]) = make_uint2(h0, h1);
        *reinterpret_cast<uint2*>(&g_Mrlo[i]) = make_uint2(l0, l1);
        return;
    }
    int w = (blockIdx.x * blockDim.x + threadIdx.x) >> 5;
    int lane = threadIdx.x & 31;
    bool first = (w < Bb * Ll);
    const float* src = first ? arg1 : arg2;
    int row = first ? w : w - Bb * Ll;
    int woff = first ? 0 : Dd;
    __nv_bfloat16* dh = first ? g_A1hi : g_B2hi;
    __nv_bfloat16* dl = first ? g_A1lo : g_B2lo;

    float aw[8] = {0,0,0,0,0,0,0,0}, av[8] = {0,0,0,0,0,0,0,0};
    const float* srow = src + (size_t)row * Dd;
#pragma unroll
    for (int q = 0; q < 4; q++) {
        int d0 = (q * 32 + lane) * 4;
        float4 x = *reinterpret_cast<const float4*>(srow + d0);
        uint32_t h0, l0, h1, l1;
        split2(x.x, x.y, h0, l0);
        split2(x.z, x.w, h1, l1);
        *reinterpret_cast<uint2*>(&dh[(size_t)row * Dd + d0]) = make_uint2(h0, h1);
        *reinterpret_cast<uint2*>(&dl[(size_t)row * Dd + d0]) = make_uint2(l0, l1);
        float xs[4] = {x.x, x.y, x.z, x.w};
#pragma unroll
        for (int e = 0; e < 4; e++) {
            int d = d0 + e;
            const float4* wp = reinterpret_cast<const float4*>(Wg + (size_t)(woff + d) * Ss);
            const float4* vp = reinterpret_cast<const float4*>(V  + (size_t)(woff + d) * Ss);
            float4 w0 = wp[0], w1 = wp[1], v0 = vp[0], v1 = vp[1];
            float xv = xs[e];
            aw[0] += xv*w0.x; aw[1] += xv*w0.y; aw[2] += xv*w0.z; aw[3] += xv*w0.w;
            aw[4] += xv*w1.x; aw[5] += xv*w1.y; aw[6] += xv*w1.z; aw[7] += xv*w1.w;
            av[0] += xv*v0.x; av[1] += xv*v0.y; av[2] += xv*v0.z; av[3] += xv*v0.w;
            av[4] += xv*v1.x; av[5] += xv*v1.y; av[6] += xv*v1.z; av[7] += xv*v1.w;
        }
    }
#pragma unroll
    for (int s = 0; s < 8; s++)
#pragma unroll
        for (int o = 16; o > 0; o >>= 1) {
            aw[s] += __shfl_xor_sync(0xffffffffu, aw[s], o);
            av[s] += __shfl_xor_sync(0xffffffffu, av[s], o);
        }
    if (lane == 0) {
        if (first) {
#pragma unroll
            for (int s = 0; s < 8; s++) {
                g_P1[(size_t)row * Ss + s] = aw[s];
                g_Q1[(size_t)row * Ss + s] = av[s];
            }
        } else {
            int bbv = row >> 9, j = row & 511;
#pragma unroll
            for (int s = 0; s < 8; s++) {
                g_P2t[((size_t)bbv * Ss + s) * Ll + j] = aw[s];
                g_Q2t[((size_t)bbv * Ss + s) * Ll + j] = av[s];
            }
        }
    }
}

// ---------------------------------------------------------------------------
// Shared GEMM geometry: CTA 128x128, 512 thr (16 warps, 32m x 32n),
// K-chunk 32, 3-stage cp.async, 2 CTAs/SM, ONE barrier per chunk.
// SMEM rows: 64B, swizzle seg' = seg ^ ((row>>1)&3).
// ---------------------------------------------------------------------------
#define OPB   8192
#define BUFB  (4 * OPB)
#define GSMEM (3 * BUFB)

__device__ __forceinline__ uint32_t cp_dst(int t) {
    int r = t >> 2, seg = t & 3;
    return (uint32_t)(r * 64 + ((seg ^ ((r >> 1) & 3)) * 16));
}
__device__ __forceinline__ uint32_t ldsm_off(int rowBase, int lane) {
    int row = rowBase + (lane & 15);
    int seg = lane >> 4;
    return (uint32_t)(row * 64 + ((seg ^ ((row >> 1) & 3)) * 16));
}

// ---------------------------------------------------------------------------
// K2: A2 = arg2 @ Mr^T, 3-pass.
// ---------------------------------------------------------------------------
__global__ __launch_bounds__(512, 2) void gemm1_kernel() {
    extern __shared__ char smem[];
    uint32_t sb = smem_u32(smem);
    int t = threadIdx.x, lane = t & 31, wid = t >> 5;
    int bz = blockIdx.z, bbv = bz >> 3, kk = bz & 7;
    int j0 = blockIdx.y * 128, d0 = blockIdx.x * 128;
    int wm = wid & 3, wn = wid >> 2;

    int rr = t >> 2, sg = t & 3;
    uint32_t dOff = cp_dst(t);
    const __nv_bfloat16* sAh = g_B2hi + ((size_t)bbv * Ll + j0 + rr) * Dd + sg * 8;
    const __nv_bfloat16* sAl = g_B2lo + ((size_t)bbv * Ll + j0 + rr) * Dd + sg * 8;
    const __nv_bfloat16* sBh = g_Mrhi + ((size_t)kk * Dd + d0 + rr) * Dd + sg * 8;
    const __nv_bfloat16* sBl = g_Mrlo + ((size_t)kk * Dd + d0 + rr) * Dd + sg * 8;

    auto issue = [&](int c) {
        uint32_t dstb = sb + (c % 3) * BUFB;
        int e0 = c * 32;
        CP16(dstb + 0 * OPB + dOff, sAh + e0);
        CP16(dstb + 1 * OPB + dOff, sAl + e0);
        CP16(dstb + 2 * OPB + dOff, sBh + e0);
        CP16(dstb + 3 * OPB + dOff, sBl + e0);
        CPCOMMIT();
    };

    // precomputed swizzled ldsm offsets (both k16 variants)
    uint32_t aO[2][2], bO[2][2];
#pragma unroll
    for (int mt = 0; mt < 2; mt++) {
        uint32_t v = ldsm_off(wm * 32 + mt * 16, lane);
        aO[mt][0] = v; aO[mt][1] = v ^ 32;
    }
#pragma unroll
    for (int nt = 0; nt < 2; nt++) {
        uint32_t v = ldsm_off(wn * 32 + nt * 16, lane);
        bO[nt][0] = v; bO[nt][1] = v ^ 32;
    }

    float acc[2][4][4];
#pragma unroll
    for (int mt = 0; mt < 2; mt++)
#pragma unroll
        for (int n8 = 0; n8 < 4; n8++)
#pragma unroll
            for (int q = 0; q < 4; q++) acc[mt][n8][q] = 0.f;

    issue(0); issue(1);
#pragma unroll 1
    for (int c = 0; c < 16; c++) {
        CPWAIT1();
        __syncthreads();
        if (c < 14) issue(c + 2); else CPCOMMIT();
        uint32_t bufb = sb + (c % 3) * BUFB;
#pragma unroll
        for (int k16 = 0; k16 < 2; k16++) {
            uint32_t ahi[2][4], alo[2][4], bhi[2][4], blo[2][4];
#pragma unroll
            for (int mt = 0; mt < 2; mt++) {
                ldsm4(ahi[mt], bufb + aO[mt][k16]);
                ldsm4(alo[mt], bufb + OPB + aO[mt][k16]);
            }
#pragma unroll
            for (int nt = 0; nt < 2; nt++) {
                ldsm4(bhi[nt], bufb + 2 * OPB + bO[nt][k16]);
                ldsm4(blo[nt], bufb + 3 * OPB + bO[nt][k16]);
            }
#pragma unroll
            for (int mt = 0; mt < 2; mt++)
#pragma unroll
                for (int n8 = 0; n8 < 4; n8++) {
                    uint32_t bh[2] = {bhi[n8 >> 1][n8 & 1], bhi[n8 >> 1][(n8 & 1) + 2]};
                    mma_bf16(acc[mt][n8], ahi[mt], bh);
                }
#pragma unroll
            for (int mt = 0; mt < 2; mt++)
#pragma unroll
                for (int n8 = 0; n8 < 4; n8++) {
                    uint32_t bl[2] = {blo[n8 >> 1][n8 & 1], blo[n8 >> 1][(n8 & 1) + 2]};
                    mma_bf16(acc[mt][n8], ahi[mt], bl);
                }
#pragma unroll
            for (int mt = 0; mt < 2; mt++)
#pragma unroll
                for (int n8 = 0; n8 < 4; n8++) {
                    uint32_t bh[2] = {bhi[n8 >> 1][n8 & 1], bhi[n8 >> 1][(n8 & 1) + 2]};
                    mma_bf16(acc[mt][n8], alo[mt], bh);
                }
        }
        // no bottom barrier: top barrier of next chunk protects buffer reuse
    }

    size_t plane = (size_t)bz * Ll * Dd;
#pragma unroll
    for (int mt = 0; mt < 2; mt++) {
        int jr = j0 + wm * 32 + mt * 16 + (lane >> 2);
#pragma unroll
        for (int n8 = 0; n8 < 4; n8++) {
            int dc = d0 + wn * 32 + n8 * 8 + (lane & 3) * 2;
            size_t x0 = plane + (size_t)jr * Dd + dc;
            size_t x1 = x0 + (size_t)8 * Dd;
            uint32_t h, l;
            split2(acc[mt][n8][0], acc[mt][n8][1], h, l);
            *reinterpret_cast<uint32_t*>(&g_A2hi[x0]) = h;
            *reinterpret_cast<uint32_t*>(&g_A2lo[x0]) = l;
            split2(acc[mt][n8][2], acc[mt][n8][3], h, l);
            *reinterpret_cast<uint32_t*>(&g_A2hi[x1]) = h;
            *reinterpret_cast<uint32_t*>(&g_A2lo[x1]) = l;
        }
    }
}

// ---------------------------------------------------------------------------
// K3: bi = arg1 @ A2^T (8 planes) + fused epilogue (same geometry).
// ---------------------------------------------------------------------------
__global__ __launch_bounds__(512, 2) void gemm2_kernel(const float* __restrict__ Bg,
                                                       const float* __restrict__ bvec,
                                                       const float* __restrict__ U,
                                                       float* __restrict__ out) {
    extern __shared__ char smem[];
    uint32_t sb = smem_u32(smem);
    int t = threadIdx.x, lane = t & 31, wid = t >> 5;
    int bbv = blockIdx.z, i0 = blockIdx.y * 128, j0 = blockIdx.x * 128;
    int wi = wid & 3, wj = wid >> 2;

    int rr = t >> 2, sg = t & 3;
    uint32_t dOff = cp_dst(t);
    const __nv_bfloat16* aHi = g_A1hi + ((size_t)bbv * Ll + i0 + rr) * Dd + sg * 8;
    const __nv_bfloat16* aLo = g_A1lo + ((size_t)bbv * Ll + i0 + rr) * Dd + sg * 8;
    const __nv_bfloat16* bHi = g_A2hi + ((size_t)(bbv * 8) * Ll + j0 + rr) * Dd + sg * 8;
    const __nv_bfloat16* bLo = g_A2lo + ((size_t)(bbv * 8) * Ll + j0 + rr) * Dd + sg * 8;

    auto issue = [&](int m) {
        int k = m >> 4;
        int e0 = (m & 15) * 32;
        uint32_t dstb = sb + (m % 3) * BUFB;
        size_t pk = (size_t)k * (Ll * Dd) + e0;
        CP16(dstb + 0 * OPB + dOff, aHi + e0);
        CP16(dstb + 1 * OPB + dOff, aLo + e0);
        CP16(dstb + 2 * OPB + dOff, bHi + pk);
        CP16(dstb + 3 * OPB + dOff, bLo + pk);
        CPCOMMIT();
    };

    uint32_t aO[2][2], bO[2][2];
#pragma unroll
    for (int mt = 0; mt < 2; mt++) {
        uint32_t v = ldsm_off(wi * 32 + mt * 16, lane);
        aO[mt][0] = v; aO[mt][1] = v ^ 32;
    }
#pragma unroll
    for (int nt = 0; nt < 2; nt++) {
        uint32_t v = ldsm_off(wj * 32 + nt * 16, lane);
        bO[nt][0] = v; bO[nt][1] = v ^ 32;
    }

    float bU = 0.f;
#pragma unroll
    for (int s = 0; s < 8; s++) bU += bvec[s] * U[s];

    float acc[2][4][4], sc[2][4][4];
#pragma unroll
    for (int mt = 0; mt < 2; mt++)
#pragma unroll
        for (int n8 = 0; n8 < 4; n8++)
#pragma unroll
            for (int q = 0; q < 4; q++) { acc[mt][n8][q] = 0.f; sc[mt][n8][q] = bU; }

    issue(0); issue(1);
#pragma unroll 1
    for (int m = 0; m < 128; m++) {
        CPWAIT1();
        __syncthreads();
        if (m < 126) issue(m + 2); else CPCOMMIT();
        uint32_t bufb = sb + (m % 3) * BUFB;
#pragma unroll
        for (int k16 = 0; k16 < 2; k16++) {
            uint32_t ahi[2][4], alo[2][4], bhi[2][4], blo[2][4];
#pragma unroll
            for (int mt = 0; mt < 2; mt++) {
                ldsm4(ahi[mt], bufb + aO[mt][k16]);
                ldsm4(alo[mt], bufb + OPB + aO[mt][k16]);
            }
#pragma unroll
            for (int nt = 0; nt < 2; nt++) {
                ldsm4(bhi[nt], bufb + 2 * OPB + bO[nt][k16]);
                ldsm4(blo[nt], bufb + 3 * OPB + bO[nt][k16]);
            }
#pragma unroll
            for (int mt = 0; mt < 2; mt++)
#pragma unroll
                for (int n8 = 0; n8 < 4; n8++) {
                    uint32_t bh[2] = {bhi[n8 >> 1][n8 & 1], bhi[n8 >> 1][(n8 & 1) + 2]};
                    mma_bf16(acc[mt][n8], ahi[mt], bh);
                }
#pragma unroll
            for (int mt = 0; mt < 2; mt++)
#pragma unroll
                for (int n8 = 0; n8 < 4; n8++) {
                    uint32_t bl[2] = {blo[n8 >> 1][n8 & 1], blo[n8 >> 1][(n8 & 1) + 2]};
                    mma_bf16(acc[mt][n8], ahi[mt], bl);
                }
#pragma unroll
            for (int mt = 0; mt < 2; mt++)
#pragma unroll
                for (int n8 = 0; n8 < 4; n8++) {
                    uint32_t bh[2] = {bhi[n8 >> 1][n8 & 1], bhi[n8 >> 1][(n8 & 1) + 2]};
                    mma_bf16(acc[mt][n8], alo[mt], bh);
                }
        }
        // no bottom barrier

        if ((m & 15) == 15) {
            int k = m >> 4;
            float BgK = Bg[k], Uk = U[k];
            const float* p2b = g_P2t + ((size_t)(bbv * 8 + k)) * Ll + j0 + wj * 32;
            const float* q2b = g_Q2t + ((size_t)(bbv * 8 + k)) * Ll + j0 + wj * 32;
#pragma unroll
            for (int mt = 0; mt < 2; mt++) {
                int iL = i0 + wi * 32 + mt * 16 + (lane >> 2);
                int iH = iL + 8;
                float p1L = g_P1[((size_t)bbv * Ll + iL) * Ss + k] + BgK;
                float p1H = g_P1[((size_t)bbv * Ll + iH) * Ss + k] + BgK;
                float q1L = g_Q1[((size_t)bbv * Ll + iL) * Ss + k];
                float q1H = g_Q1[((size_t)bbv * Ll + iH) * Ss + k];
#pragma unroll
                for (int n8 = 0; n8 < 4; n8++)
#pragma unroll
                    for (int e = 0; e < 2; e++) {
                        int jc = n8 * 8 + (lane & 3) * 2 + e;
                        float p2 = p2b[jc], q2 = q2b[jc];
                        float gL = sig_fma(p1L + p2), sL = sig_fma(q1L + q2);
                        float gH = sig_fma(p1H + p2), sH = sig_fma(q1H + q2);
                        sc[mt][n8][e]     += Uk * fmaf(acc[mt][n8][e] - sL, gL, sL);
                        sc[mt][n8][2 + e] += Uk * fmaf(acc[mt][n8][2 + e] - sH, gH, sH);
                        acc[mt][n8][e] = 0.f;
                        acc[mt][n8][2 + e] = 0.f;
                    }
            }
        }
    }

    // Final sigmoid + store
#pragma unroll
    for (int mt = 0; mt < 2; mt++) {
        int iL = i0 + wi * 32 + mt * 16 + (lane >> 2);
        int iH = iL + 8;
#pragma unroll
        for (int n8 = 0; n8 < 4; n8++) {
            int jc = j0 + wj * 32 + n8 * 8 + (lane & 3) * 2;
            float2 v0 = make_float2(sig_fma(sc[mt][n8][0]), sig_fma(sc[mt][n8][1]));
            float2 v1 = make_float2(sig_fma(sc[mt][n8][2]), sig_fma(sc[mt][n8][3]));
            *reinterpret_cast<float2*>(&out[((size_t)bbv * Ll + iL) * Ll + jc]) = v0;
            *reinterpret_cast<float2*>(&out[((size_t)bbv * Ll + iH) * Ll + jc]) = v1;
        }
    }
}

// ---------------------------------------------------------------------------
extern "C" void kernel_launch(void* const* d_in, const int* in_sizes, int n_in,
                              void* d_out, int out_size) {
    const float* arg1 = (const float*)d_in[0];
    const float* arg2 = (const float*)d_in[1];
    const float* Wg   = (const float*)d_in[2];
    const float* Bg   = (const float*)d_in[3];
    const float* Mr   = (const float*)d_in[4];
    const float* V    = (const float*)d_in[5];
    const float* bvec = (const float*)d_in[6];
    const float* U    = (const float*)d_in[7];
    float* out = (float*)d_out;

    cudaFuncSetAttribute(gemm1_kernel, cudaFuncAttributeMaxDynamicSharedMemorySize, GSMEM);
    cudaFuncSetAttribute(gemm2_kernel, cudaFuncAttributeMaxDynamicSharedMemorySize, GSMEM);

    // proj (4096 blocks) + Mr split (2048 blocks) in one launch
    conv_proj_kernel<<<4096 + 2048, 256>>>(arg1, arg2, Wg, V, Mr);

    dim3 g1(Dd / 128, Ll / 128, Bb * Ss);
    gemm1_kernel<<<g1, 512, GSMEM>>>();

    dim3 g2(Ll / 128, Ll / 128, Bb);
    gemm2_kernel<<<g2, 512, GSMEM>>>(Bg, bvec, U, out);
}

// round 16
// speedup vs baseline: 1.9468x; 1.1069x over previous
#include <cuda_runtime.h>
#include <cuda_bf16.h>
#include <cstdint>

#define Bb 32
#define Ll 512
#define Dd 512
#define Ss 8

// ---------------------------------------------------------------------------
// Device-global scratch
// ---------------------------------------------------------------------------
__device__ __nv_bfloat16 g_A2hi[(size_t)Bb * Ss * Ll * Dd];
__device__ __nv_bfloat16 g_A2lo[(size_t)Bb * Ss * Ll * Dd];
__device__ __nv_bfloat16 g_A1hi[(size_t)Bb * Ll * Dd];
__device__ __nv_bfloat16 g_A1lo[(size_t)Bb * Ll * Dd];
__device__ __nv_bfloat16 g_B2hi[(size_t)Bb * Ll * Dd];
__device__ __nv_bfloat16 g_B2lo[(size_t)Bb * Ll * Dd];
__device__ __nv_bfloat16 g_Mrhi[(size_t)Ss * Dd * Dd];
__device__ __nv_bfloat16 g_Mrlo[(size_t)Ss * Dd * Dd];
__device__ float g_P1[Bb * Ll * Ss];
__device__ float g_Q1[Bb * Ll * Ss];
__device__ float g_P2t[Bb * Ss * Ll];
__device__ float g_Q2t[Bb * Ss * Ll];

// ---------------------------------------------------------------------------
// Helpers
// ---------------------------------------------------------------------------
__device__ __forceinline__ uint32_t smem_u32(const void* p) {
    uint32_t a;
    asm("{ .reg .u64 t; cvta.to.shared.u64 t, %1; cvt.u32.u64 %0, t; }"
        : "=r"(a) : "l"(p));
    return a;
}
__device__ __forceinline__ void ldsm4(uint32_t* r, uint32_t a) {
    asm volatile("ldmatrix.sync.aligned.m8n8.x4.shared.b16 {%0,%1,%2,%3}, [%4];"
                 : "=r"(r[0]), "=r"(r[1]), "=r"(r[2]), "=r"(r[3]) : "r"(a) : "memory");
}
__device__ __forceinline__ void mma_bf16(float* c, const uint32_t* a, const uint32_t* b) {
    asm volatile("mma.sync.aligned.m16n8k16.row.col.f32.bf16.bf16.f32 "
                 "{%0,%1,%2,%3}, {%4,%5,%6,%7}, {%8,%9}, {%0,%1,%2,%3};"
                 : "+f"(c[0]), "+f"(c[1]), "+f"(c[2]), "+f"(c[3])
                 : "r"(a[0]), "r"(a[1]), "r"(a[2]), "r"(a[3]), "r"(b[0]), "r"(b[1]));
}
#define CP16(dst, src) \
    asm volatile("cp.async.cg.shared.global [%0], [%1], 16;" :: "r"(dst), "l"(src) : "memory")
#define CPCOMMIT() asm volatile("cp.async.commit_group;" ::: "memory")
#define CPWAIT1() asm volatile("cp.async.wait_group 1;" ::: "memory")

__device__ __forceinline__ uint32_t pack_bf16x2(float a, float b) {
    uint32_t h;
    asm("cvt.rn.bf16x2.f32 %0, %1, %2;" : "=r"(h) : "f"(b), "f"(a));
    return h;
}
__device__ __forceinline__ void split2(float a, float b, uint32_t& h, uint32_t& l) {
    h = pack_bf16x2(a, b);
    float ha = __uint_as_float(h << 16), hb = __uint_as_float(h & 0xFFFF0000u);
    l = pack_bf16x2(a - ha, b - hb);
}

// FMA-pipe-only sigmoid, abs err ~1.5e-5
__device__ __forceinline__ float sig_fma(float x) {
    float ax = fminf(fabsf(x), 20.0f);
    float y = -1.44269504f * ax;
    float t = y + 12582912.0f;
    int n = __float_as_int(t) - 0x4B400000;
    float f = y - (t - 12582912.0f);
    float p = 1.33335581e-3f;
    p = fmaf(p, f, 9.61812910e-3f);
    p = fmaf(p, f, 5.55041086e-2f);
    p = fmaf(p, f, 2.40226507e-1f);
    p = fmaf(p, f, 6.93147181e-1f);
    p = fmaf(p, f, 1.0f);
    float E = __int_as_float(__float_as_int(p) + (n << 23));
    float w = 1.0f + E;
    float r = __int_as_float(0x7EF127EAu - __float_as_int(w));
    r = r * (2.0f - w * r);
    r = r * (2.0f - w * r);
    return x >= 0.0f ? r : 1.0f - r;
}

// ---------------------------------------------------------------------------
// K1: fused projections + input split + Mr split.
// Blocks [0, 1024): proj, 8 warps/block, 4 rows per warp (weight reuse x4).
// Blocks [1024, 3072): Mr split.
// ---------------------------------------------------------------------------
__global__ void conv_proj_kernel(const float* __restrict__ arg1,
                                 const float* __restrict__ arg2,
                                 const float* __restrict__ Wg,
                                 const float* __restrict__ V,
                                 const float* __restrict__ Mr) {
    if (blockIdx.x >= 1024) {
        size_t i = ((size_t)(blockIdx.x - 1024) * 256 + threadIdx.x) * 4;
        float4 v = *reinterpret_cast<const float4*>(Mr + i);
        uint32_t h0, l0, h1, l1;
        split2(v.x, v.y, h0, l0);
        split2(v.z, v.w, h1, l1);
        *reinterpret_cast<uint2*>(&g_Mrhi[i]) = make_uint2(h0, h1);
        *reinterpret_cast<uint2*>(&g_Mrlo[i]) = make_uint2(l0, l1);
        return;
    }
    int wid = threadIdx.x >> 5;
    int lane = threadIdx.x & 31;
    int rowBase = (blockIdx.x * 8 + wid) * 4;      // 4 consecutive rows
    bool first = (rowBase < Bb * Ll);
    const float* src = first ? arg1 : arg2;
    int row0 = first ? rowBase : rowBase - Bb * Ll;
    int woff = first ? 0 : Dd;
    __nv_bfloat16* dh = first ? g_A1hi : g_B2hi;
    __nv_bfloat16* dl = first ? g_A1lo : g_B2lo;

    float aw[4][8], av[4][8];
#pragma unroll
    for (int r = 0; r < 4; r++)
#pragma unroll
        for (int s = 0; s < 8; s++) { aw[r][s] = 0.f; av[r][s] = 0.f; }

#pragma unroll
    for (int q = 0; q < 4; q++) {
        int d0 = (q * 32 + lane) * 4;
        float xs[4][4];
#pragma unroll
        for (int r = 0; r < 4; r++) {
            float4 x = *reinterpret_cast<const float4*>(src + (size_t)(row0 + r) * Dd + d0);
            xs[r][0] = x.x; xs[r][1] = x.y; xs[r][2] = x.z; xs[r][3] = x.w;
            uint32_t h0, l0, h1, l1;
            split2(x.x, x.y, h0, l0);
            split2(x.z, x.w, h1, l1);
            *reinterpret_cast<uint2*>(&dh[(size_t)(row0 + r) * Dd + d0]) = make_uint2(h0, h1);
            *reinterpret_cast<uint2*>(&dl[(size_t)(row0 + r) * Dd + d0]) = make_uint2(l0, l1);
        }
#pragma unroll
        for (int e = 0; e < 4; e++) {
            int d = d0 + e;
            const float4* wp = reinterpret_cast<const float4*>(Wg + (size_t)(woff + d) * Ss);
            const float4* vp = reinterpret_cast<const float4*>(V  + (size_t)(woff + d) * Ss);
            float4 w0 = wp[0], w1 = wp[1], v0 = vp[0], v1 = vp[1];
#pragma unroll
            for (int r = 0; r < 4; r++) {
                float xv = xs[r][e];
                aw[r][0] += xv*w0.x; aw[r][1] += xv*w0.y; aw[r][2] += xv*w0.z; aw[r][3] += xv*w0.w;
                aw[r][4] += xv*w1.x; aw[r][5] += xv*w1.y; aw[r][6] += xv*w1.z; aw[r][7] += xv*w1.w;
                av[r][0] += xv*v0.x; av[r][1] += xv*v0.y; av[r][2] += xv*v0.z; av[r][3] += xv*v0.w;
                av[r][4] += xv*v1.x; av[r][5] += xv*v1.y; av[r][6] += xv*v1.z; av[r][7] += xv*v1.w;
            }
        }
    }
#pragma unroll
    for (int r = 0; r < 4; r++)
#pragma unroll
        for (int s = 0; s < 8; s++)
#pragma unroll
            for (int o = 16; o > 0; o >>= 1) {
                aw[r][s] += __shfl_xor_sync(0xffffffffu, aw[r][s], o);
                av[r][s] += __shfl_xor_sync(0xffffffffu, av[r][s], o);
            }
    if (lane == 0) {
#pragma unroll
        for (int r = 0; r < 4; r++) {
            int row = row0 + r;
            if (first) {
#pragma unroll
                for (int s = 0; s < 8; s++) {
                    g_P1[(size_t)row * Ss + s] = aw[r][s];
                    g_Q1[(size_t)row * Ss + s] = av[r][s];
                }
            } else {
                int bbv = row >> 9, j = row & 511;
#pragma unroll
                for (int s = 0; s < 8; s++) {
                    g_P2t[((size_t)bbv * Ss + s) * Ll + j] = aw[r][s];
                    g_Q2t[((size_t)bbv * Ss + s) * Ll + j] = av[r][s];
                }
            }
        }
    }
}

// ---------------------------------------------------------------------------
// Shared GEMM geometry: CTA 128x128, 512 thr (16 warps, 32m x 32n),
// K-chunk 32, 3-stage cp.async, 2 CTAs/SM, ONE barrier per chunk.
// SMEM rows: 64B, swizzle seg' = seg ^ ((row>>1)&3).
// ---------------------------------------------------------------------------
#define OPB   8192
#define BUFB  (4 * OPB)
#define GSMEM (3 * BUFB)

__device__ __forceinline__ uint32_t cp_dst(int t) {
    int r = t >> 2, seg = t & 3;
    return (uint32_t)(r * 64 + ((seg ^ ((r >> 1) & 3)) * 16));
}
__device__ __forceinline__ uint32_t ldsm_off(int rowBase, int lane) {
    int row = rowBase + (lane & 15);
    int seg = lane >> 4;
    return (uint32_t)(row * 64 + ((seg ^ ((row >> 1) & 3)) * 16));
}

// ---------------------------------------------------------------------------
// K2: A2 = arg2 @ Mr^T, 3-pass.
// ---------------------------------------------------------------------------
__global__ __launch_bounds__(512, 2) void gemm1_kernel() {
    extern __shared__ char smem[];
    uint32_t sb = smem_u32(smem);
    int t = threadIdx.x, lane = t & 31, wid = t >> 5;
    int bz = blockIdx.z, bbv = bz >> 3, kk = bz & 7;
    int j0 = blockIdx.y * 128, d0 = blockIdx.x * 128;
    int wm = wid & 3, wn = wid >> 2;

    int rr = t >> 2, sg = t & 3;
    uint32_t dOff = cp_dst(t);
    const __nv_bfloat16* sAh = g_B2hi + ((size_t)bbv * Ll + j0 + rr) * Dd + sg * 8;
    const __nv_bfloat16* sAl = g_B2lo + ((size_t)bbv * Ll + j0 + rr) * Dd + sg * 8;
    const __nv_bfloat16* sBh = g_Mrhi + ((size_t)kk * Dd + d0 + rr) * Dd + sg * 8;
    const __nv_bfloat16* sBl = g_Mrlo + ((size_t)kk * Dd + d0 + rr) * Dd + sg * 8;

    auto issue = [&](int c) {
        uint32_t dstb = sb + (c % 3) * BUFB;
        int e0 = c * 32;
        CP16(dstb + 0 * OPB + dOff, sAh + e0);
        CP16(dstb + 1 * OPB + dOff, sAl + e0);
        CP16(dstb + 2 * OPB + dOff, sBh + e0);
        CP16(dstb + 3 * OPB + dOff, sBl + e0);
        CPCOMMIT();
    };

    uint32_t aO[2][2], bO[2][2];
#pragma unroll
    for (int mt = 0; mt < 2; mt++) {
        uint32_t v = ldsm_off(wm * 32 + mt * 16, lane);
        aO[mt][0] = v; aO[mt][1] = v ^ 32;
    }
#pragma unroll
    for (int nt = 0; nt < 2; nt++) {
        uint32_t v = ldsm_off(wn * 32 + nt * 16, lane);
        bO[nt][0] = v; bO[nt][1] = v ^ 32;
    }

    float acc[2][4][4];
#pragma unroll
    for (int mt = 0; mt < 2; mt++)
#pragma unroll
        for (int n8 = 0; n8 < 4; n8++)
#pragma unroll
            for (int q = 0; q < 4; q++) acc[mt][n8][q] = 0.f;

    issue(0); issue(1);
#pragma unroll 1
    for (int c = 0; c < 16; c++) {
        CPWAIT1();
        __syncthreads();
        if (c < 14) issue(c + 2); else CPCOMMIT();
        uint32_t bufb = sb + (c % 3) * BUFB;
#pragma unroll
        for (int k16 = 0; k16 < 2; k16++) {
            uint32_t ahi[2][4], alo[2][4], bhi[2][4], blo[2][4];
#pragma unroll
            for (int mt = 0; mt < 2; mt++) {
                ldsm4(ahi[mt], bufb + aO[mt][k16]);
                ldsm4(alo[mt], bufb + OPB + aO[mt][k16]);
            }
#pragma unroll
            for (int nt = 0; nt < 2; nt++) {
                ldsm4(bhi[nt], bufb + 2 * OPB + bO[nt][k16]);
                ldsm4(blo[nt], bufb + 3 * OPB + bO[nt][k16]);
            }
#pragma unroll
            for (int mt = 0; mt < 2; mt++)
#pragma unroll
                for (int n8 = 0; n8 < 4; n8++) {
                    uint32_t bh[2] = {bhi[n8 >> 1][n8 & 1], bhi[n8 >> 1][(n8 & 1) + 2]};
                    mma_bf16(acc[mt][n8], ahi[mt], bh);
                }
#pragma unroll
            for (int mt = 0; mt < 2; mt++)
#pragma unroll
                for (int n8 = 0; n8 < 4; n8++) {
                    uint32_t bl[2] = {blo[n8 >> 1][n8 & 1], blo[n8 >> 1][(n8 & 1) + 2]};
                    mma_bf16(acc[mt][n8], ahi[mt], bl);
                }
#pragma unroll
            for (int mt = 0; mt < 2; mt++)
#pragma unroll
                for (int n8 = 0; n8 < 4; n8++) {
                    uint32_t bh[2] = {bhi[n8 >> 1][n8 & 1], bhi[n8 >> 1][(n8 & 1) + 2]};
                    mma_bf16(acc[mt][n8], alo[mt], bh);
                }
        }
    }

    size_t plane = (size_t)bz * Ll * Dd;
#pragma unroll
    for (int mt = 0; mt < 2; mt++) {
        int jr = j0 + wm * 32 + mt * 16 + (lane >> 2);
#pragma unroll
        for (int n8 = 0; n8 < 4; n8++) {
            int dc = d0 + wn * 32 + n8 * 8 + (lane & 3) * 2;
            size_t x0 = plane + (size_t)jr * Dd + dc;
            size_t x1 = x0 + (size_t)8 * Dd;
            uint32_t h, l;
            split2(acc[mt][n8][0], acc[mt][n8][1], h, l);
            *reinterpret_cast<uint32_t*>(&g_A2hi[x0]) = h;
            *reinterpret_cast<uint32_t*>(&g_A2lo[x0]) = l;
            split2(acc[mt][n8][2], acc[mt][n8][3], h, l);
            *reinterpret_cast<uint32_t*>(&g_A2hi[x1]) = h;
            *reinterpret_cast<uint32_t*>(&g_A2lo[x1]) = l;
        }
    }
}

// ---------------------------------------------------------------------------
// K3: bi = arg1 @ A2^T (8 planes) + fused epilogue (same geometry).
// ---------------------------------------------------------------------------
__global__ __launch_bounds__(512, 2) void gemm2_kernel(const float* __restrict__ Bg,
                                                       const float* __restrict__ bvec,
                                                       const float* __restrict__ U,
                                                       float* __restrict__ out) {
    extern __shared__ char smem[];
    uint32_t sb = smem_u32(smem);
    int t = threadIdx.x, lane = t & 31, wid = t >> 5;
    int bbv = blockIdx.z, i0 = blockIdx.y * 128, j0 = blockIdx.x * 128;
    int wi = wid & 3, wj = wid >> 2;

    int rr = t >> 2, sg = t & 3;
    uint32_t dOff = cp_dst(t);
    const __nv_bfloat16* aHi = g_A1hi + ((size_t)bbv * Ll + i0 + rr) * Dd + sg * 8;
    const __nv_bfloat16* aLo = g_A1lo + ((size_t)bbv * Ll + i0 + rr) * Dd + sg * 8;
    const __nv_bfloat16* bHi = g_A2hi + ((size_t)(bbv * 8) * Ll + j0 + rr) * Dd + sg * 8;
    const __nv_bfloat16* bLo = g_A2lo + ((size_t)(bbv * 8) * Ll + j0 + rr) * Dd + sg * 8;

    auto issue = [&](int m) {
        int k = m >> 4;
        int e0 = (m & 15) * 32;
        uint32_t dstb = sb + (m % 3) * BUFB;
        size_t pk = (size_t)k * (Ll * Dd) + e0;
        CP16(dstb + 0 * OPB + dOff, aHi + e0);
        CP16(dstb + 1 * OPB + dOff, aLo + e0);
        CP16(dstb + 2 * OPB + dOff, bHi + pk);
        CP16(dstb + 3 * OPB + dOff, bLo + pk);
        CPCOMMIT();
    };

    uint32_t aO[2][2], bO[2][2];
#pragma unroll
    for (int mt = 0; mt < 2; mt++) {
        uint32_t v = ldsm_off(wi * 32 + mt * 16, lane);
        aO[mt][0] = v; aO[mt][1] = v ^ 32;
    }
#pragma unroll
    for (int nt = 0; nt < 2; nt++) {
        uint32_t v = ldsm_off(wj * 32 + nt * 16, lane);
        bO[nt][0] = v; bO[nt][1] = v ^ 32;
    }

    float bU = 0.f;
#pragma unroll
    for (int s = 0; s < 8; s++) bU += bvec[s] * U[s];

    float acc[2][4][4], sc[2][4][4];
#pragma unroll
    for (int mt = 0; mt < 2; mt++)
#pragma unroll
        for (int n8 = 0; n8 < 4; n8++)
#pragma unroll
            for (int q = 0; q < 4; q++) { acc[mt][n8][q] = 0.f; sc[mt][n8][q] = bU; }

    issue(0); issue(1);
#pragma unroll 1
    for (int m = 0; m < 128; m++) {
        CPWAIT1();
        __syncthreads();
        if (m < 126) issue(m + 2); else CPCOMMIT();
        uint32_t bufb = sb + (m % 3) * BUFB;
#pragma unroll
        for (int k16 = 0; k16 < 2; k16++) {
            uint32_t ahi[2][4], alo[2][4], bhi[2][4], blo[2][4];
#pragma unroll
            for (int mt = 0; mt < 2; mt++) {
                ldsm4(ahi[mt], bufb + aO[mt][k16]);
                ldsm4(alo[mt], bufb + OPB + aO[mt][k16]);
            }
#pragma unroll
            for (int nt = 0; nt < 2; nt++) {
                ldsm4(bhi[nt], bufb + 2 * OPB + bO[nt][k16]);
                ldsm4(blo[nt], bufb + 3 * OPB + bO[nt][k16]);
            }
#pragma unroll
            for (int mt = 0; mt < 2; mt++)
#pragma unroll
                for (int n8 = 0; n8 < 4; n8++) {
                    uint32_t bh[2] = {bhi[n8 >> 1][n8 & 1], bhi[n8 >> 1][(n8 & 1) + 2]};
                    mma_bf16(acc[mt][n8], ahi[mt], bh);
                }
#pragma unroll
            for (int mt = 0; mt < 2; mt++)
#pragma unroll
                for (int n8 = 0; n8 < 4; n8++) {
                    uint32_t bl[2] = {blo[n8 >> 1][n8 & 1], blo[n8 >> 1][(n8 & 1) + 2]};
                    mma_bf16(acc[mt][n8], ahi[mt], bl);
                }
#pragma unroll
            for (int mt = 0; mt < 2; mt++)
#pragma unroll
                for (int n8 = 0; n8 < 4; n8++) {
                    uint32_t bh[2] = {bhi[n8 >> 1][n8 & 1], bhi[n8 >> 1][(n8 & 1) + 2]};
                    mma_bf16(acc[mt][n8], alo[mt], bh);
                }
        }

        if ((m & 15) == 15) {
            int k = m >> 4;
            float BgK = Bg[k], Uk = U[k];
            const float* p2b = g_P2t + ((size_t)(bbv * 8 + k)) * Ll + j0 + wj * 32;
            const float* q2b = g_Q2t + ((size_t)(bbv * 8 + k)) * Ll + j0 + wj * 32;
#pragma unroll
            for (int mt = 0; mt < 2; mt++) {
                int iL = i0 + wi * 32 + mt * 16 + (lane >> 2);
                int iH = iL + 8;
                float p1L = g_P1[((size_t)bbv * Ll + iL) * Ss + k] + BgK;
                float p1H = g_P1[((size_t)bbv * Ll + iH) * Ss + k] + BgK;
                float q1L = g_Q1[((size_t)bbv * Ll + iL) * Ss + k];
                float q1H = g_Q1[((size_t)bbv * Ll + iH) * Ss + k];
#pragma unroll
                for (int n8 = 0; n8 < 4; n8++)
#pragma unroll
                    for (int e = 0; e < 2; e++) {
                        int jc = n8 * 8 + (lane & 3) * 2 + e;
                        float p2 = p2b[jc], q2 = q2b[jc];
                        float gL = sig_fma(p1L + p2), sL = sig_fma(q1L + q2);
                        float gH = sig_fma(p1H + p2), sH = sig_fma(q1H + q2);
                        sc[mt][n8][e]     += Uk * fmaf(acc[mt][n8][e] - sL, gL, sL);
                        sc[mt][n8][2 + e] += Uk * fmaf(acc[mt][n8][2 + e] - sH, gH, sH);
                        acc[mt][n8][e] = 0.f;
                        acc[mt][n8][2 + e] = 0.f;
                    }
            }
        }
    }

    // Final sigmoid + store
#pragma unroll
    for (int mt = 0; mt < 2; mt++) {
        int iL = i0 + wi * 32 + mt * 16 + (lane >> 2);
        int iH = iL + 8;
#pragma unroll
        for (int n8 = 0; n8 < 4; n8++) {
            int jc = j0 + wj * 32 + n8 * 8 + (lane & 3) * 2;
            float2 v0 = make_float2(sig_fma(sc[mt][n8][0]), sig_fma(sc[mt][n8][1]));
            float2 v1 = make_float2(sig_fma(sc[mt][n8][2]), sig_fma(sc[mt][n8][3]));
            *reinterpret_cast<float2*>(&out[((size_t)bbv * Ll + iL) * Ll + jc]) = v0;
            *reinterpret_cast<float2*>(&out[((size_t)bbv * Ll + iH) * Ll + jc]) = v1;
        }
    }
}

// ---------------------------------------------------------------------------
extern "C" void kernel_launch(void* const* d_in, const int* in_sizes, int n_in,
                              void* d_out, int out_size) {
    const float* arg1 = (const float*)d_in[0];
    const float* arg2 = (const float*)d_in[1];
    const float* Wg   = (const float*)d_in[2];
    const float* Bg   = (const float*)d_in[3];
    const float* Mr   = (const float*)d_in[4];
    const float* V    = (const float*)d_in[5];
    const float* bvec = (const float*)d_in[6];
    const float* U    = (const float*)d_in[7];
    float* out = (float*)d_out;

    cudaFuncSetAttribute(gemm1_kernel, cudaFuncAttributeMaxDynamicSharedMemorySize, GSMEM);
    cudaFuncSetAttribute(gemm2_kernel, cudaFuncAttributeMaxDynamicSharedMemorySize, GSMEM);

    // proj (1024 blocks, 4 rows/warp) + Mr split (2048 blocks) in one launch
    conv_proj_kernel<<<1024 + 2048, 256>>>(arg1, arg2, Wg, V, Mr);

    dim3 g1(Dd / 128, Ll / 128, Bb * Ss);
    gemm1_kernel<<<g1, 512, GSMEM>>>();

    dim3 g2(Ll / 128, Ll / 128, Bb);
    gemm2_kernel<<<g2, 512, GSMEM>>>(Bg, bvec, U, out);
}

// round 17
// speedup vs baseline: 2.0014x; 1.0280x over previous
#include <cuda_runtime.h>
#include <cuda_bf16.h>
#include <cstdint>

#define Bb 32
#define Ll 512
#define Dd 512
#define Ss 8

// ---------------------------------------------------------------------------
// Device-global scratch
// ---------------------------------------------------------------------------
__device__ __nv_bfloat16 g_A2hi[(size_t)Bb * Ss * Ll * Dd];
__device__ __nv_bfloat16 g_A2lo[(size_t)Bb * Ss * Ll * Dd];
__device__ __nv_bfloat16 g_A1hi[(size_t)Bb * Ll * Dd];
__device__ __nv_bfloat16 g_A1lo[(size_t)Bb * Ll * Dd];
__device__ __nv_bfloat16 g_B2hi[(size_t)Bb * Ll * Dd];
__device__ __nv_bfloat16 g_B2lo[(size_t)Bb * Ll * Dd];
__device__ __nv_bfloat16 g_Mrhi[(size_t)Ss * Dd * Dd];
__device__ __nv_bfloat16 g_Mrlo[(size_t)Ss * Dd * Dd];
__device__ float g_P1[Bb * Ll * Ss];
__device__ float g_Q1[Bb * Ll * Ss];
__device__ float g_P2t[Bb * Ss * Ll];
__device__ float g_Q2t[Bb * Ss * Ll];

// ---------------------------------------------------------------------------
// Helpers
// ---------------------------------------------------------------------------
__device__ __forceinline__ uint32_t smem_u32(const void* p) {
    uint32_t a;
    asm("{ .reg .u64 t; cvta.to.shared.u64 t, %1; cvt.u32.u64 %0, t; }"
        : "=r"(a) : "l"(p));
    return a;
}
__device__ __forceinline__ void ldsm4(uint32_t* r, uint32_t a) {
    asm volatile("ldmatrix.sync.aligned.m8n8.x4.shared.b16 {%0,%1,%2,%3}, [%4];"
                 : "=r"(r[0]), "=r"(r[1]), "=r"(r[2]), "=r"(r[3]) : "r"(a) : "memory");
}
__device__ __forceinline__ void mma_bf16(float* c, const uint32_t* a, const uint32_t* b) {
    asm volatile("mma.sync.aligned.m16n8k16.row.col.f32.bf16.bf16.f32 "
                 "{%0,%1,%2,%3}, {%4,%5,%6,%7}, {%8,%9}, {%0,%1,%2,%3};"
                 : "+f"(c[0]), "+f"(c[1]), "+f"(c[2]), "+f"(c[3])
                 : "r"(a[0]), "r"(a[1]), "r"(a[2]), "r"(a[3]), "r"(b[0]), "r"(b[1]));
}
#define CP16(dst, src) \
    asm volatile("cp.async.cg.shared.global [%0], [%1], 16;" :: "r"(dst), "l"(src) : "memory")
#define CPCOMMIT() asm volatile("cp.async.commit_group;" ::: "memory")
#define CPWAIT1() asm volatile("cp.async.wait_group 1;" ::: "memory")
#define CPWAIT0() asm volatile("cp.async.wait_group 0;" ::: "memory")

__device__ __forceinline__ uint32_t pack_bf16x2(float a, float b) {
    uint32_t h;
    asm("cvt.rn.bf16x2.f32 %0, %1, %2;" : "=r"(h) : "f"(b), "f"(a));
    return h;
}
__device__ __forceinline__ void split2(float a, float b, uint32_t& h, uint32_t& l) {
    h = pack_bf16x2(a, b);
    float ha = __uint_as_float(h << 16), hb = __uint_as_float(h & 0xFFFF0000u);
    l = pack_bf16x2(a - ha, b - hb);
}

// FMA-pipe-only sigmoid, abs err ~1.5e-5
__device__ __forceinline__ float sig_fma(float x) {
    float ax = fminf(fabsf(x), 20.0f);
    float y = -1.44269504f * ax;
    float t = y + 12582912.0f;
    int n = __float_as_int(t) - 0x4B400000;
    float f = y - (t - 12582912.0f);
    float p = 1.33335581e-3f;
    p = fmaf(p, f, 9.61812910e-3f);
    p = fmaf(p, f, 5.55041086e-2f);
    p = fmaf(p, f, 2.40226507e-1f);
    p = fmaf(p, f, 6.93147181e-1f);
    p = fmaf(p, f, 1.0f);
    float E = __int_as_float(__float_as_int(p) + (n << 23));
    float w = 1.0f + E;
    float r = __int_as_float(0x7EF127EAu - __float_as_int(w));
    r = r * (2.0f - w * r);
    r = r * (2.0f - w * r);
    return x >= 0.0f ? r : 1.0f - r;
}

// ---------------------------------------------------------------------------
// K1: fused projections + input split + Mr split (unchanged from R16).
// ---------------------------------------------------------------------------
__global__ void conv_proj_kernel(const float* __restrict__ arg1,
                                 const float* __restrict__ arg2,
                                 const float* __restrict__ Wg,
                                 const float* __restrict__ V,
                                 const float* __restrict__ Mr) {
    if (blockIdx.x >= 1024) {
        size_t i = ((size_t)(blockIdx.x - 1024) * 256 + threadIdx.x) * 4;
        float4 v = *reinterpret_cast<const float4*>(Mr + i);
        uint32_t h0, l0, h1, l1;
        split2(v.x, v.y, h0, l0);
        split2(v.z, v.w, h1, l1);
        *reinterpret_cast<uint2*>(&g_Mrhi[i]) = make_uint2(h0, h1);
        *reinterpret_cast<uint2*>(&g_Mrlo[i]) = make_uint2(l0, l1);
        return;
    }
    int wid = threadIdx.x >> 5;
    int lane = threadIdx.x & 31;
    int rowBase = (blockIdx.x * 8 + wid) * 4;
    bool first = (rowBase < Bb * Ll);
    const float* src = first ? arg1 : arg2;
    int row0 = first ? rowBase : rowBase - Bb * Ll;
    int woff = first ? 0 : Dd;
    __nv_bfloat16* dh = first ? g_A1hi : g_B2hi;
    __nv_bfloat16* dl = first ? g_A1lo : g_B2lo;

    float aw[4][8], av[4][8];
#pragma unroll
    for (int r = 0; r < 4; r++)
#pragma unroll
        for (int s = 0; s < 8; s++) { aw[r][s] = 0.f; av[r][s] = 0.f; }

#pragma unroll
    for (int q = 0; q < 4; q++) {
        int d0 = (q * 32 + lane) * 4;
        float xs[4][4];
#pragma unroll
        for (int r = 0; r < 4; r++) {
            float4 x = *reinterpret_cast<const float4*>(src + (size_t)(row0 + r) * Dd + d0);
            xs[r][0] = x.x; xs[r][1] = x.y; xs[r][2] = x.z; xs[r][3] = x.w;
            uint32_t h0, l0, h1, l1;
            split2(x.x, x.y, h0, l0);
            split2(x.z, x.w, h1, l1);
            *reinterpret_cast<uint2*>(&dh[(size_t)(row0 + r) * Dd + d0]) = make_uint2(h0, h1);
            *reinterpret_cast<uint2*>(&dl[(size_t)(row0 + r) * Dd + d0]) = make_uint2(l0, l1);
        }
#pragma unroll
        for (int e = 0; e < 4; e++) {
            int d = d0 + e;
            const float4* wp = reinterpret_cast<const float4*>(Wg + (size_t)(woff + d) * Ss);
            const float4* vp = reinterpret_cast<const float4*>(V  + (size_t)(woff + d) * Ss);
            float4 w0 = wp[0], w1 = wp[1], v0 = vp[0], v1 = vp[1];
#pragma unroll
            for (int r = 0; r < 4; r++) {
                float xv = xs[r][e];
                aw[r][0] += xv*w0.x; aw[r][1] += xv*w0.y; aw[r][2] += xv*w0.z; aw[r][3] += xv*w0.w;
                aw[r][4] += xv*w1.x; aw[r][5] += xv*w1.y; aw[r][6] += xv*w1.z; aw[r][7] += xv*w1.w;
                av[r][0] += xv*v0.x; av[r][1] += xv*v0.y; av[r][2] += xv*v0.z; av[r][3] += xv*v0.w;
                av[r][4] += xv*v1.x; av[r][5] += xv*v1.y; av[r][6] += xv*v1.z; av[r][7] += xv*v1.w;
            }
        }
    }
#pragma unroll
    for (int r = 0; r < 4; r++)
#pragma unroll
        for (int s = 0; s < 8; s++)
#pragma unroll
            for (int o = 16; o > 0; o >>= 1) {
                aw[r][s] += __shfl_xor_sync(0xffffffffu, aw[r][s], o);
                av[r][s] += __shfl_xor_sync(0xffffffffu, av[r][s], o);
            }
    if (lane == 0) {
#pragma unroll
        for (int r = 0; r < 4; r++) {
            int row = row0 + r;
            if (first) {
#pragma unroll
                for (int s = 0; s < 8; s++) {
                    g_P1[(size_t)row * Ss + s] = aw[r][s];
                    g_Q1[(size_t)row * Ss + s] = av[r][s];
                }
            } else {
                int bbv = row >> 9, j = row & 511;
#pragma unroll
                for (int s = 0; s < 8; s++) {
                    g_P2t[((size_t)bbv * Ss + s) * Ll + j] = aw[r][s];
                    g_Q2t[((size_t)bbv * Ss + s) * Ll + j] = av[r][s];
                }
            }
        }
    }
}

// ---------------------------------------------------------------------------
// K2: A2 = arg2 @ Mr^T, 3-pass (unchanged from R16).
// CTA 128x128, 512 thr (32m x 32n warps), K-chunk 32, 3-stage, 2 CTA/SM.
// ---------------------------------------------------------------------------
#define OPB   8192
#define BUFB  (4 * OPB)
#define GSMEM (3 * BUFB)

__device__ __forceinline__ uint32_t cp_dst(int t) {
    int r = t >> 2, seg = t & 3;
    return (uint32_t)(r * 64 + ((seg ^ ((r >> 1) & 3)) * 16));
}
__device__ __forceinline__ uint32_t ldsm_off(int rowBase, int lane) {
    int row = rowBase + (lane & 15);
    int seg = lane >> 4;
    return (uint32_t)(row * 64 + ((seg ^ ((row >> 1) & 3)) * 16));
}

__global__ __launch_bounds__(512, 2) void gemm1_kernel() {
    extern __shared__ char smem[];
    uint32_t sb = smem_u32(smem);
    int t = threadIdx.x, lane = t & 31, wid = t >> 5;
    int bz = blockIdx.z, bbv = bz >> 3, kk = bz & 7;
    int j0 = blockIdx.y * 128, d0 = blockIdx.x * 128;
    int wm = wid & 3, wn = wid >> 2;

    int rr = t >> 2, sg = t & 3;
    uint32_t dOff = cp_dst(t);
    const __nv_bfloat16* sAh = g_B2hi + ((size_t)bbv * Ll + j0 + rr) * Dd + sg * 8;
    const __nv_bfloat16* sAl = g_B2lo + ((size_t)bbv * Ll + j0 + rr) * Dd + sg * 8;
    const __nv_bfloat16* sBh = g_Mrhi + ((size_t)kk * Dd + d0 + rr) * Dd + sg * 8;
    const __nv_bfloat16* sBl = g_Mrlo + ((size_t)kk * Dd + d0 + rr) * Dd + sg * 8;

    auto issue = [&](int c) {
        uint32_t dstb = sb + (c % 3) * BUFB;
        int e0 = c * 32;
        CP16(dstb + 0 * OPB + dOff, sAh + e0);
        CP16(dstb + 1 * OPB + dOff, sAl + e0);
        CP16(dstb + 2 * OPB + dOff, sBh + e0);
        CP16(dstb + 3 * OPB + dOff, sBl + e0);
        CPCOMMIT();
    };

    uint32_t aO[2][2], bO[2][2];
#pragma unroll
    for (int mt = 0; mt < 2; mt++) {
        uint32_t v = ldsm_off(wm * 32 + mt * 16, lane);
        aO[mt][0] = v; aO[mt][1] = v ^ 32;
    }
#pragma unroll
    for (int nt = 0; nt < 2; nt++) {
        uint32_t v = ldsm_off(wn * 32 + nt * 16, lane);
        bO[nt][0] = v; bO[nt][1] = v ^ 32;
    }

    float acc[2][4][4];
#pragma unroll
    for (int mt = 0; mt < 2; mt++)
#pragma unroll
        for (int n8 = 0; n8 < 4; n8++)
#pragma unroll
            for (int q = 0; q < 4; q++) acc[mt][n8][q] = 0.f;

    issue(0); issue(1);
#pragma unroll 1
    for (int c = 0; c < 16; c++) {
        CPWAIT1();
        __syncthreads();
        if (c < 14) issue(c + 2); else CPCOMMIT();
        uint32_t bufb = sb + (c % 3) * BUFB;
#pragma unroll
        for (int k16 = 0; k16 < 2; k16++) {
            uint32_t ahi[2][4], alo[2][4], bhi[2][4], blo[2][4];
#pragma unroll
            for (int mt = 0; mt < 2; mt++) {
                ldsm4(ahi[mt], bufb + aO[mt][k16]);
                ldsm4(alo[mt], bufb + OPB + aO[mt][k16]);
            }
#pragma unroll
            for (int nt = 0; nt < 2; nt++) {
                ldsm4(bhi[nt], bufb + 2 * OPB + bO[nt][k16]);
                ldsm4(blo[nt], bufb + 3 * OPB + bO[nt][k16]);
            }
#pragma unroll
            for (int mt = 0; mt < 2; mt++)
#pragma unroll
                for (int n8 = 0; n8 < 4; n8++) {
                    uint32_t bh[2] = {bhi[n8 >> 1][n8 & 1], bhi[n8 >> 1][(n8 & 1) + 2]};
                    mma_bf16(acc[mt][n8], ahi[mt], bh);
                }
#pragma unroll
            for (int mt = 0; mt < 2; mt++)
#pragma unroll
                for (int n8 = 0; n8 < 4; n8++) {
                    uint32_t bl[2] = {blo[n8 >> 1][n8 & 1], blo[n8 >> 1][(n8 & 1) + 2]};
                    mma_bf16(acc[mt][n8], ahi[mt], bl);
                }
#pragma unroll
            for (int mt = 0; mt < 2; mt++)
#pragma unroll
                for (int n8 = 0; n8 < 4; n8++) {
                    uint32_t bh[2] = {bhi[n8 >> 1][n8 & 1], bhi[n8 >> 1][(n8 & 1) + 2]};
                    mma_bf16(acc[mt][n8], alo[mt], bh);
                }
        }
    }

    size_t plane = (size_t)bz * Ll * Dd;
#pragma unroll
    for (int mt = 0; mt < 2; mt++) {
        int jr = j0 + wm * 32 + mt * 16 + (lane >> 2);
#pragma unroll
        for (int n8 = 0; n8 < 4; n8++) {
            int dc = d0 + wn * 32 + n8 * 8 + (lane & 3) * 2;
            size_t x0 = plane + (size_t)jr * Dd + dc;
            size_t x1 = x0 + (size_t)8 * Dd;
            uint32_t h, l;
            split2(acc[mt][n8][0], acc[mt][n8][1], h, l);
            *reinterpret_cast<uint32_t*>(&g_A2hi[x0]) = h;
            *reinterpret_cast<uint32_t*>(&g_A2lo[x0]) = l;
            split2(acc[mt][n8][2], acc[mt][n8][3], h, l);
            *reinterpret_cast<uint32_t*>(&g_A2hi[x1]) = h;
            *reinterpret_cast<uint32_t*>(&g_A2lo[x1]) = l;
        }
    }
}

// ---------------------------------------------------------------------------
// K3 REWORKED: bi = arg1 @ A2^T (8 planes) + fused epilogue.
// CTA 128i x 32j, 512 thr (16 warps = 8m x 2n, warp tile 16i x 16j).
// K-chunk 64, 2-stage cp.async, 2 CTA/SM. Grid 2048 => 6.9 waves (98.8%).
// SMEM rows 128B, swizzle seg' = seg ^ (row & 7).
// Stage: Ahi(16K) | Alo(16K) | Bhi(4K) | Blo(4K) = 40KB; 2 stages = 80KB.
// ---------------------------------------------------------------------------
#define S2_AOP  16384
#define S2_BOP  4096
#define S2_STG  (2 * S2_AOP + 2 * S2_BOP)   // 40960
#define S2_SMEM (2 * S2_STG)                // 81920

__global__ __launch_bounds__(512, 2) void gemm2_kernel(const float* __restrict__ Bg,
                                                       const float* __restrict__ bvec,
                                                       const float* __restrict__ U,
                                                       float* __restrict__ out) {
    extern __shared__ char smem[];
    uint32_t sb = smem_u32(smem);
    int t = threadIdx.x, lane = t & 31, wid = t >> 5;
    int bbv = blockIdx.z, i0 = blockIdx.y * 128, j0 = blockIdx.x * 32;
    int wm = wid & 7, wn = wid >> 3;

    // cp.async: A (arg1 split): 2 slots per variant per thread.
    int ra0 = t >> 3, sa = t & 7;
    int ra1 = ra0 + 64;
    const __nv_bfloat16* aHi0 = g_A1hi + ((size_t)bbv * Ll + i0 + ra0) * Dd + sa * 8;
    const __nv_bfloat16* aHi1 = g_A1hi + ((size_t)bbv * Ll + i0 + ra1) * Dd + sa * 8;
    const __nv_bfloat16* aLo0 = g_A1lo + ((size_t)bbv * Ll + i0 + ra0) * Dd + sa * 8;
    const __nv_bfloat16* aLo1 = g_A1lo + ((size_t)bbv * Ll + i0 + ra1) * Dd + sa * 8;
    uint32_t dA0 = (uint32_t)(ra0 * 128 + ((sa ^ (ra0 & 7)) * 16));
    uint32_t dA1 = (uint32_t)(ra1 * 128 + ((sa ^ (ra1 & 7)) * 16));
    // B (A2 split): 1 slot per thread; t<256 -> hi, t>=256 -> lo.
    int rb = (t & 255) >> 3;
    int bvar = t >> 8;
    const __nv_bfloat16* bP = (bvar ? g_A2lo : g_A2hi)
        + ((size_t)(bbv * 8) * Ll + j0 + rb) * Dd + sa * 8;
    uint32_t dB = (uint32_t)(2 * S2_AOP + bvar * S2_BOP
                             + rb * 128 + ((sa ^ (rb & 7)) * 16));

    auto issue = [&](int m) {
        int k = m >> 3;
        int e0 = (m & 7) * 64;
        uint32_t dstb = sb + (m & 1) * S2_STG;
        CP16(dstb + dA0, aHi0 + e0);
        CP16(dstb + dA1, aHi1 + e0);
        CP16(dstb + S2_AOP + dA0, aLo0 + e0);
        CP16(dstb + S2_AOP + dA1, aLo1 + e0);
        CP16(dstb + dB, bP + (size_t)k * (Ll * Dd) + e0);
        CPCOMMIT();
    };

    // ldsm offsets (4 k16 positions within a 64-col chunk)
    int arow = wm * 16 + (lane & 15);
    int brow = wn * 16 + (lane & 15);
    uint32_t aoff[4], boff[4];
#pragma unroll
    for (int c16 = 0; c16 < 4; c16++) {
        int cc = c16 * 2 + (lane >> 4);
        aoff[c16] = (uint32_t)(arow * 128 + ((cc ^ (arow & 7)) * 16));
        boff[c16] = (uint32_t)(2 * S2_AOP + brow * 128 + ((cc ^ (brow & 7)) * 16));
    }

    float bU = 0.f;
#pragma unroll
    for (int s = 0; s < 8; s++) bU += bvec[s] * U[s];

    float acc[2][4], sc[2][4];
#pragma unroll
    for (int n8 = 0; n8 < 2; n8++)
#pragma unroll
        for (int q = 0; q < 4; q++) { acc[n8][q] = 0.f; sc[n8][q] = bU; }

    issue(0);
#pragma unroll 1
    for (int m = 0; m < 64; m++) {
        CPWAIT0();
        __syncthreads();
        if (m < 63) issue(m + 1);
        uint32_t bufb = sb + (m & 1) * S2_STG;
#pragma unroll
        for (int c16 = 0; c16 < 4; c16++) {
            uint32_t ahi[4], alo[4], bh4[4], bl4[4];
            ldsm4(ahi, bufb + aoff[c16]);
            ldsm4(alo, bufb + S2_AOP + aoff[c16]);
            ldsm4(bh4, bufb + boff[c16]);
            ldsm4(bl4, bufb + S2_BOP + boff[c16]);
#pragma unroll
            for (int n8 = 0; n8 < 2; n8++) {
                uint32_t bh[2] = {bh4[n8], bh4[n8 + 2]};
                mma_bf16(acc[n8], ahi, bh);
            }
#pragma unroll
            for (int n8 = 0; n8 < 2; n8++) {
                uint32_t bl[2] = {bl4[n8], bl4[n8 + 2]};
                mma_bf16(acc[n8], ahi, bl);
            }
#pragma unroll
            for (int n8 = 0; n8 < 2; n8++) {
                uint32_t bh[2] = {bh4[n8], bh4[n8 + 2]};
                mma_bf16(acc[n8], alo, bh);
            }
        }

        if ((m & 7) == 7) {
            // plane k complete: fused gated epilogue into sc, reset acc
            int k = m >> 3;
            float BgK = Bg[k], Uk = U[k];
            int iL = i0 + wm * 16 + (lane >> 2);
            int iH = iL + 8;
            float p1L = g_P1[((size_t)bbv * Ll + iL) * Ss + k] + BgK;
            float p1H = g_P1[((size_t)bbv * Ll + iH) * Ss + k] + BgK;
            float q1L = g_Q1[((size_t)bbv * Ll + iL) * Ss + k];
            float q1H = g_Q1[((size_t)bbv * Ll + iH) * Ss + k];
            const float* p2b = g_P2t + ((size_t)(bbv * 8 + k)) * Ll + j0 + wn * 16;
            const float* q2b = g_Q2t + ((size_t)(bbv * 8 + k)) * Ll + j0 + wn * 16;
#pragma unroll
            for (int n8 = 0; n8 < 2; n8++)
#pragma unroll
                for (int e = 0; e < 2; e++) {
                    int jc = n8 * 8 + (lane & 3) * 2 + e;
                    float p2 = p2b[jc], q2 = q2b[jc];
                    float gL = sig_fma(p1L + p2), sL = sig_fma(q1L + q2);
                    float gH = sig_fma(p1H + p2), sH = sig_fma(q1H + q2);
                    sc[n8][e]     += Uk * fmaf(acc[n8][e] - sL, gL, sL);
                    sc[n8][2 + e] += Uk * fmaf(acc[n8][2 + e] - sH, gH, sH);
                    acc[n8][e] = 0.f;
                    acc[n8][2 + e] = 0.f;
                }
        }
    }

    // Final sigmoid + store
    {
        int iL = i0 + wm * 16 + (lane >> 2);
        int iH = iL + 8;
#pragma unroll
        for (int n8 = 0; n8 < 2; n8++) {
            int jc = j0 + wn * 16 + n8 * 8 + (lane & 3) * 2;
            float2 v0 = make_float2(sig_fma(sc[n8][0]), sig_fma(sc[n8][1]));
            float2 v1 = make_float2(sig_fma(sc[n8][2]), sig_fma(sc[n8][3]));
            *reinterpret_cast<float2*>(&out[((size_t)bbv * Ll + iL) * Ll + jc]) = v0;
            *reinterpret_cast<float2*>(&out[((size_t)bbv * Ll + iH) * Ll + jc]) = v1;
        }
    }
}

// ---------------------------------------------------------------------------
extern "C" void kernel_launch(void* const* d_in, const int* in_sizes, int n_in,
                              void* d_out, int out_size) {
    const float* arg1 = (const float*)d_in[0];
    const float* arg2 = (const float*)d_in[1];
    const float* Wg   = (const float*)d_in[2];
    const float* Bg   = (const float*)d_in[3];
    const float* Mr   = (const float*)d_in[4];
    const float* V    = (const float*)d_in[5];
    const float* bvec = (const float*)d_in[6];
    const float* U    = (const float*)d_in[7];
    float* out = (float*)d_out;

    cudaFuncSetAttribute(gemm1_kernel, cudaFuncAttributeMaxDynamicSharedMemorySize, GSMEM);
    cudaFuncSetAttribute(gemm2_kernel, cudaFuncAttributeMaxDynamicSharedMemorySize, S2_SMEM);

    conv_proj_kernel<<<1024 + 2048, 256>>>(arg1, arg2, Wg, V, Mr);

    dim3 g1(Dd / 128, Ll / 128, Bb * Ss);
    gemm1_kernel<<<g1, 512, GSMEM>>>();

    dim3 g2(Ll / 32, Ll / 128, Bb);
    gemm2_kernel<<<g2, 512, S2_SMEM>>>(Bg, bvec, U, out);
}